// round 14
// baseline (speedup 1.0000x reference)
#include <cuda_runtime.h>
#include <cuda_bf16.h>
#include <cuda_fp16.h>
#include <cstdint>
#include <math.h>

#define BATCH 2
#define SEQ   2048
#define NH    16
#define DHEAD 64
#define DMODEL 1024
#define MROWS (BATCH*SEQ)   // 4096

// ---------------- scratch (device globals; no allocation allowed) ----------
__device__ float g_v[MROWS*DMODEL];
__device__ __half g_aqh[MROWS*DMODEL];
__device__ __half g_aql[MROWS*DMODEL];
__device__ __half g_akh[MROWS*DMODEL];
__device__ __half g_akl[MROWS*DMODEL];
__device__ __half g_avh[MROWS*DMODEL];
__device__ __half g_avl[MROWS*DMODEL];
__device__ __half g_wqh[DMODEL*DMODEL];
__device__ __half g_wkh[DMODEL*DMODEL];
__device__ __half g_wvh[DMODEL*DMODEL];
__device__ __half g_qh[MROWS*DMODEL];
__device__ __half g_ql[MROWS*DMODEL];
__device__ __half g_kh[MROWS*DMODEL];
__device__ __half g_vth[MROWS*DMODEL];      // V^T [b][h][d][s]
__device__ __half g_vtl[MROWS*DMODEL];

// ======================= helpers ===========================================
__device__ __forceinline__ uint32_t s2u(const void* p) {
    uint32_t a;
    asm("{ .reg .u64 t; cvta.to.shared.u64 t, %1; cvt.u32.u64 %0, t; }"
        : "=r"(a) : "l"(p));
    return a;
}
__device__ __forceinline__ void cp16(uint32_t d, const void* s) {
    asm volatile("cp.async.cg.shared.global [%0], [%1], 16;\n" :: "r"(d), "l"(s));
}
__device__ __forceinline__ void cpcommit() {
    asm volatile("cp.async.commit_group;\n" ::: "memory");
}
__device__ __forceinline__ void cpwait1() {
    asm volatile("cp.async.wait_group 1;\n" ::: "memory");
}
__device__ __forceinline__ void cpwait0() {
    asm volatile("cp.async.wait_group 0;\n" ::: "memory");
}
__device__ __forceinline__ void ldsm4(uint32_t* r, uint32_t addr) {
    asm volatile("ldmatrix.sync.aligned.m8n8.x4.shared.b16 {%0,%1,%2,%3}, [%4];"
        : "=r"(r[0]), "=r"(r[1]), "=r"(r[2]), "=r"(r[3]) : "r"(addr));
}
__device__ __forceinline__ void mma_f16(float* d, const uint32_t* a,
                                        uint32_t b0, uint32_t b1) {
    asm volatile(
        "mma.sync.aligned.m16n8k16.row.col.f32.f16.f16.f32 "
        "{%0,%1,%2,%3}, {%4,%5,%6,%7}, {%8,%9}, {%0,%1,%2,%3};"
        : "+f"(d[0]), "+f"(d[1]), "+f"(d[2]), "+f"(d[3])
        : "r"(a[0]), "r"(a[1]), "r"(a[2]), "r"(a[3]), "r"(b0), "r"(b1));
}
// fp16 split pair (x low, y high)
__device__ __forceinline__ void split2h(float x, float y,
                                        uint32_t& hi, uint32_t& lo) {
    __half2 H = __floats2half2_rn(x, y);
    __half2 L = __floats2half2_rn(x - __half2float(__low2half(H)),
                                  y - __half2float(__high2half(H)));
    hi = *(uint32_t*)&H;
    lo = *(uint32_t*)&L;
}
__device__ __forceinline__ uint32_t packh(float x, float y) {
    __half2 H = __floats2half2_rn(x, y);
    return *(uint32_t*)&H;
}

// ======================= split conversion kernels ==========================
__global__ __launch_bounds__(256)
void split3_kernel(const float* __restrict__ X0, const float* __restrict__ X1,
                   const float* __restrict__ X2,
                   __half* H0, __half* L0,
                   __half* H1, __half* L1,
                   __half* H2, __half* L2, int n4)
{
    int z = blockIdx.y;
    const float* X = z == 0 ? X0 : (z == 1 ? X1 : X2);
    __half* hi = z == 0 ? H0 : (z == 1 ? H1 : H2);
    __half* lo = z == 0 ? L0 : (z == 1 ? L1 : L2);
    int i = blockIdx.x * 256 + threadIdx.x;
    if (i >= n4) return;
    float4 v = ((const float4*)X)[i];
    uint32_t h0, l0, h1, l1;
    split2h(v.x, v.y, h0, l0);
    split2h(v.z, v.w, h1, l1);
    ((uint32_t*)hi)[2*i]   = h0;  ((uint32_t*)hi)[2*i+1] = h1;
    ((uint32_t*)lo)[2*i]   = l0;  ((uint32_t*)lo)[2*i+1] = l1;
}

// transpose: W[K,N] -> WT[N,K] as fp16 hi only (z selects matrix)
__global__ __launch_bounds__(256)
void wtsplit3_kernel(const float* __restrict__ W0, const float* __restrict__ W1,
                     const float* __restrict__ W2,
                     __half* H0, __half* H1, __half* H2)
{
    int z = blockIdx.z;
    const float* W = z == 0 ? W0 : (z == 1 ? W1 : W2);
    __half* wth = z == 0 ? H0 : (z == 1 ? H1 : H2);
    __shared__ float tile[32][33];
    int tx = threadIdx.x & 31, ty = threadIdx.x >> 5;  // 32x8
    int n0 = blockIdx.x * 32, k0 = blockIdx.y * 32;
#pragma unroll
    for (int i = 0; i < 4; i++)
        tile[ty + 8*i][tx] = W[(size_t)(k0 + ty + 8*i) * DMODEL + n0 + tx];
    __syncthreads();
#pragma unroll
    for (int i = 0; i < 4; i++) {
        float x = tile[tx][ty + 8*i];
        size_t o = (size_t)(n0 + ty + 8*i) * DMODEL + k0 + tx;
        wth[o] = __float2half_rn(x);
    }
}

// transpose + split V: V[b][s][h*64+d] -> Vt[b][h][d][s] fp16 hi/lo
__global__ __launch_bounds__(256)
void vtsplit_kernel(const float* __restrict__ V,
                    __half* __restrict__ vth,
                    __half* __restrict__ vtl)
{
    __shared__ float tile[32][33];
    int tx = threadIdx.x & 31, ty = threadIdx.x >> 5;  // 32x8
    int s0 = blockIdx.x * 32, d0 = blockIdx.y * 32, b = blockIdx.z;
#pragma unroll
    for (int i = 0; i < 4; i++)
        tile[ty + 8*i][tx] = V[((size_t)(b*SEQ) + s0 + ty + 8*i) * DMODEL + d0 + tx];
    __syncthreads();
#pragma unroll
    for (int i = 0; i < 4; i++) {
        int d = d0 + ty + 8*i;
        float x = tile[tx][ty + 8*i];
        __half h = __float2half_rn(x);
        __half l = __float2half_rn(x - __half2float(h));
        int hh = d >> 6, dl = d & 63;
        size_t o = (((size_t)(b*NH + hh) * DHEAD + dl)) * SEQ + s0 + tx;
        vth[o] = h;
        vtl[o] = l;
    }
}

// ======================= fp16 HMMA GEMM: C = A @ W^T + bias ================
// 2-pass: Ah*Wh + Al*Wh. W hi only. KC=64. 3-stage pipeline, 1 sync/chunk.
#define KC 64
#define ASTB 144                        // 64 halves (128B) + 16B pad
#define TILE_B (128*ASTB)               // 18432
#define STAGE_B (3*TILE_B)              // 55296 : Ah, Al, Wh
#define GEMM_SMEM (3*STAGE_B)           // 165888
#define NCH (DMODEL/KC)                 // 16

// out modes: 0 = fp32 C, 2 = fp16 hi/lo, 3 = fp16 hi only
struct GemmJob {
    const __half *Ah, *Al, *Bh;
    const float* bias;
    float* C;
    __half *Ch, *Cl;
    int mode;
};

__global__ __launch_bounds__(256)
void gemm_mma_kernel(GemmJob j0, GemmJob j1, GemmJob j2)
{
    const GemmJob J = (blockIdx.z == 0) ? j0 : (blockIdx.z == 1 ? j1 : j2);
    extern __shared__ char smem[];
    const uint32_t sb = s2u(smem);
    const int t = threadIdx.x, w = t >> 5, l = t & 31;
    const int row0 = blockIdx.y * 128, col0 = blockIdx.x * 128;
    const int wm = (w & 1) * 64;
    const int wn = (w >> 1) * 32;

    float acc[4][4][4];
#pragma unroll
    for (int mt = 0; mt < 4; mt++)
#pragma unroll
        for (int nt = 0; nt < 4; nt++)
#pragma unroll
            for (int k = 0; k < 4; k++) acc[mt][nt][k] = 0.f;

    auto load_stage = [&](int c, int st) {
        const uint32_t base = sb + st * STAGE_B;
        const int kc = c * KC;
#pragma unroll
        for (int i = 0; i < 4; i++) {
            int u = t + i * 256;                 // 0..1023
            int r = u >> 3, j = u & 7;           // row, 16B chunk (8 per row)
            uint32_t dso = (uint32_t)(r * ASTB + j * 16);
            size_t ga = (size_t)(row0 + r) * DMODEL + kc + j * 8;
            size_t gb = (size_t)(col0 + r) * DMODEL + kc + j * 8;
            cp16(base + dso,              J.Ah + ga);
            cp16(base + TILE_B + dso,     J.Al + ga);
            cp16(base + 2*TILE_B + dso,   J.Bh + gb);
        }
        cpcommit();
    };

    load_stage(0, 0);
    load_stage(1, 1);

    // ldmatrix lane geometry
    const int aRow   = (l & 7) + ((l >> 3) & 1) * 8;
    const int aChunk = (l >> 4) * 16;
    const int bRow   = (l & 7) + ((l >> 4) << 3);
    const int bChunk = ((l >> 3) & 1) * 16;

    for (int c = 0; c < NCH; c++) {
        if (c + 1 < NCH) cpwait1(); else cpwait0();
        __syncthreads();
        if (c + 2 < NCH) load_stage(c + 2, (c + 2) % 3);

        const uint32_t stg = sb + (c % 3) * STAGE_B;
        const uint32_t uAh = stg + (wm + aRow) * ASTB + aChunk;
        const uint32_t uAl = uAh + TILE_B;
        const uint32_t uBh = stg + 2*TILE_B + (wn + bRow) * ASTB + bChunk;

#pragma unroll
        for (int ks = 0; ks < 4; ks++) {
            const int kb = ks * 32;
            uint32_t aH[4][4], aL[4][4], bH[2][4];
#pragma unroll
            for (int mt = 0; mt < 4; mt++) {
                ldsm4(aH[mt], uAh + mt * (16*ASTB) + kb);
                ldsm4(aL[mt], uAl + mt * (16*ASTB) + kb);
            }
#pragma unroll
            for (int p = 0; p < 2; p++)
                ldsm4(bH[p], uBh + p * (16*ASTB) + kb);
#pragma unroll
            for (int mt = 0; mt < 4; mt++)
#pragma unroll
                for (int p = 0; p < 2; p++)
#pragma unroll
                    for (int hf = 0; hf < 2; hf++) {
                        int nt = p * 2 + hf;
                        uint32_t b0h = bH[p][2*hf], b1h = bH[p][2*hf+1];
                        mma_f16(acc[mt][nt], aH[mt], b0h, b1h);
                        mma_f16(acc[mt][nt], aL[mt], b0h, b1h);
                    }
        }
    }

    const int ar = l >> 2;
#pragma unroll
    for (int mt = 0; mt < 4; mt++) {
        int gr0 = row0 + wm + mt * 16 + ar;
#pragma unroll
        for (int nt = 0; nt < 4; nt++) {
            int gc = col0 + wn + nt * 8 + (l & 3) * 2;
            float b0 = J.bias[gc], b1 = J.bias[gc + 1];
            float x0 = acc[mt][nt][0] + b0, y0 = acc[mt][nt][1] + b1;
            float x1 = acc[mt][nt][2] + b0, y1 = acc[mt][nt][3] + b1;
            size_t oA = (size_t)gr0 * DMODEL + gc;
            size_t oB = (size_t)(gr0 + 8) * DMODEL + gc;
            if (J.mode == 0) {
                *(float2*)(J.C + oA) = make_float2(x0, y0);
                *(float2*)(J.C + oB) = make_float2(x1, y1);
            } else if (J.mode == 2) {
                uint32_t h0, l0w, h1, l1w;
                split2h(x0, y0, h0, l0w);
                split2h(x1, y1, h1, l1w);
                ((uint32_t*)J.Ch)[oA >> 1] = h0;
                ((uint32_t*)J.Cl)[oA >> 1] = l0w;
                ((uint32_t*)J.Ch)[oB >> 1] = h1;
                ((uint32_t*)J.Cl)[oB >> 1] = l1w;
            } else {
                ((uint32_t*)J.Ch)[oA >> 1] = packh(x0, y0);
                ((uint32_t*)J.Ch)[oB >> 1] = packh(x1, y1);
            }
        }
    }
}

// ======================= fp16 HMMA flash attention =========================
// Q fp16 hi/lo (registers), K fp16 hi only, V fp16 hi/lo. QK 2-pass, PV 2-pass.
// 3-stage KV pipeline (stage 2 overlays the dead Q staging area), 1 sync/iter,
// 2 CTAs/SM (regs capped at 128).
#define BQ  128
#define BKV 64
#define NKV (SEQ/BKV)          // 32
#define STB 144                // smem row stride bytes (72 halves)
#define QTILE_B (128*STB)      // 18432
#define KTILE_B (64*STB)       // 9216
#define STAGE_AB (3*KTILE_B)   // 27648 : Kh, Vh, Vl
#define QOFF (2*STAGE_AB)      // 55296 : Q staging (overlaps stage 2)
#define ATTN_SMEM_B (QOFF + 2*QTILE_B)   // 92160

__global__ __launch_bounds__(256, 2)
void attn_mma_kernel(const __half* __restrict__ Qh,
                     const __half* __restrict__ Ql,
                     const __half* __restrict__ Kh,
                     const __half* __restrict__ Vth,
                     const __half* __restrict__ Vtl,
                     __half* __restrict__ Oh,
                     __half* __restrict__ Ol)
{
    extern __shared__ char smem[];
    const uint32_t sb = s2u(smem);
    const int t = threadIdx.x, w = t >> 5, l = t & 31;
    const int q0 = blockIdx.x * BQ;
    const int h  = blockIdx.y, b = blockIdx.z;
    const int r4 = l >> 2;

    auto load_kv = [&](int kvt, int st) {
        const uint32_t base = sb + st * STAGE_AB;
        int kv0 = kvt * BKV;
        const __half* KhG = Kh + ((size_t)(b*SEQ + kv0)) * DMODEL + h*DHEAD;
        const __half* VhG = Vth + ((size_t)(b*NH + h)) * DHEAD * SEQ + kv0;
        const __half* VlG = Vtl + ((size_t)(b*NH + h)) * DHEAD * SEQ + kv0;
#pragma unroll
        for (int i = 0; i < 6; i++) {
            int u = t + i * 256;               // 0..1535
            int tile = u >> 9, v = u & 511;
            int row = v >> 3, ch = v & 7;
            uint32_t dst = base + tile * KTILE_B + row * STB + ch * 16;
            const __half* src;
            if      (tile == 0) src = KhG + (size_t)row * DMODEL + ch * 8;
            else if (tile == 1) src = VhG + (size_t)row * SEQ + ch * 8;
            else                src = VlG + (size_t)row * SEQ + ch * 8;
            cp16(dst, src);
        }
        cpcommit();
    };

    // ---- prologue: Q hi/lo into (dead-after-frags) staging + stage0 as G0 --
    {
        const __half* QhG = Qh + ((size_t)(b*SEQ + q0)) * DMODEL + h*DHEAD;
        const __half* QlG = Ql + ((size_t)(b*SEQ + q0)) * DMODEL + h*DHEAD;
#pragma unroll
        for (int i = 0; i < 8; i++) {
            int u = t + i * 256;               // 0..2047
            int tile = u >> 10, v = u & 1023;
            int row = v >> 3, ch = v & 7;
            uint32_t dst = sb + QOFF + tile * QTILE_B + row * STB + ch * 16;
            const __half* src = (tile ? QlG : QhG) + (size_t)row * DMODEL + ch * 8;
            cp16(dst, src);
        }
    }
    load_kv(0, 0);      // commits G0 = {Q tiles, stage0}
    load_kv(1, 1);      // G1 = {stage1}
    cpwait1();          // G0 complete (Q + stage0)
    __syncthreads();

    // ldmatrix lane geometry
    const int aRow   = (l & 7) + ((l >> 3) & 1) * 8;
    const int aChunk = (l >> 4) * 16;
    const int bRow   = (l & 7) + ((l >> 4) << 3);
    const int bChunk = ((l >> 3) & 1) * 16;

    // ---- Q fragments (held in registers for all kv tiles) ----
    uint32_t aH[4][4], aL[4][4];
    {
        const uint32_t qoff = sb + QOFF + (w * 16 + aRow) * STB + aChunk;
#pragma unroll
        for (int s = 0; s < 4; s++) {
            ldsm4(aH[s], qoff + 32 * s);
            ldsm4(aL[s], qoff + QTILE_B + 32 * s);
        }
    }
    __syncthreads();    // all warps done reading Q before stage2 (overlay) write

    float m0 = -1e30f, m1 = -1e30f, l0 = 0.f, l1 = 0.f;
    float oacc[8][4];
#pragma unroll
    for (int j = 0; j < 8; j++)
#pragma unroll
        for (int k = 0; k < 4; k++) oacc[j][k] = 0.f;

    for (int kvt = 0; kvt < NKV; kvt++) {
        if (kvt > 0) {
            if (kvt + 1 < NKV) cpwait1(); else cpwait0();
            __syncthreads();
        }
        if (kvt + 2 < NKV) load_kv(kvt + 2, (kvt + 2) % 3);

        const uint32_t stg = sb + (kvt % 3) * STAGE_AB;
        const uint32_t uKh = stg + bRow * STB + bChunk;
        const uint32_t uVh = uKh + KTILE_B;
        const uint32_t uVl = uKh + 2*KTILE_B;

        // ---- scores: S = Q*K^T (2-pass: Qh*Kh + Ql*Kh) ----
        float sc[8][4];
#pragma unroll
        for (int j = 0; j < 8; j++)
#pragma unroll
            for (int k = 0; k < 4; k++) sc[j][k] = 0.f;

#pragma unroll
        for (int jp = 0; jp < 4; jp++) {
#pragma unroll
            for (int s = 0; s < 4; s++) {
                uint32_t kh[4];
                ldsm4(kh, uKh + jp * 2304 + 32 * s);
                mma_f16(sc[2*jp],   aH[s], kh[0], kh[1]);
                mma_f16(sc[2*jp],   aL[s], kh[0], kh[1]);
                mma_f16(sc[2*jp+1], aH[s], kh[2], kh[3]);
                mma_f16(sc[2*jp+1], aL[s], kh[2], kh[3]);
            }
        }
#pragma unroll
        for (int j = 0; j < 8; j++)
#pragma unroll
            for (int k = 0; k < 4; k++) sc[j][k] *= 0.125f;

        // ---- online softmax (rows r4 and r4+8 of this warp tile) ----
        float lm0 = -1e30f, lm1 = -1e30f;
#pragma unroll
        for (int j = 0; j < 8; j++) {
            lm0 = fmaxf(lm0, fmaxf(sc[j][0], sc[j][1]));
            lm1 = fmaxf(lm1, fmaxf(sc[j][2], sc[j][3]));
        }
        lm0 = fmaxf(lm0, __shfl_xor_sync(0xffffffffu, lm0, 1));
        lm0 = fmaxf(lm0, __shfl_xor_sync(0xffffffffu, lm0, 2));
        lm1 = fmaxf(lm1, __shfl_xor_sync(0xffffffffu, lm1, 1));
        lm1 = fmaxf(lm1, __shfl_xor_sync(0xffffffffu, lm1, 2));
        float mn0 = fmaxf(m0, lm0), mn1 = fmaxf(m1, lm1);
        float cf0 = __expf(m0 - mn0), cf1 = __expf(m1 - mn1);
        float rs0 = 0.f, rs1 = 0.f;
#pragma unroll
        for (int j = 0; j < 8; j++) {
            float p0 = __expf(sc[j][0] - mn0);
            float p1 = __expf(sc[j][1] - mn0);
            float p2 = __expf(sc[j][2] - mn1);
            float p3 = __expf(sc[j][3] - mn1);
            sc[j][0] = p0; sc[j][1] = p1; sc[j][2] = p2; sc[j][3] = p3;
            rs0 += p0 + p1;  rs1 += p2 + p3;
        }
        rs0 += __shfl_xor_sync(0xffffffffu, rs0, 1);
        rs0 += __shfl_xor_sync(0xffffffffu, rs0, 2);
        rs1 += __shfl_xor_sync(0xffffffffu, rs1, 1);
        rs1 += __shfl_xor_sync(0xffffffffu, rs1, 2);
        l0 = l0 * cf0 + rs0;  l1 = l1 * cf1 + rs1;
        m0 = mn0;  m1 = mn1;
#pragma unroll
        for (int j = 0; j < 8; j++) {
            oacc[j][0] *= cf0;  oacc[j][1] *= cf0;
            oacc[j][2] *= cf1;  oacc[j][3] *= cf1;
        }

        // ---- PV: ctx += P @ V (2-pass: P*Vh + P*Vl), P plain fp16 ----
#pragma unroll
        for (int s = 0; s < 4; s++) {
            uint32_t pH[4];
            pH[0] = packh(sc[2*s][0],   sc[2*s][1]);
            pH[1] = packh(sc[2*s][2],   sc[2*s][3]);
            pH[2] = packh(sc[2*s+1][0], sc[2*s+1][1]);
            pH[3] = packh(sc[2*s+1][2], sc[2*s+1][3]);
#pragma unroll
            for (int jp = 0; jp < 4; jp++) {
                uint32_t vh[4], vl[4];
                ldsm4(vh, uVh + jp * 2304 + 32 * s);
                ldsm4(vl, uVl + jp * 2304 + 32 * s);
                mma_f16(oacc[2*jp],   pH, vh[0], vh[1]);
                mma_f16(oacc[2*jp],   pH, vl[0], vl[1]);
                mma_f16(oacc[2*jp+1], pH, vh[2], vh[3]);
                mma_f16(oacc[2*jp+1], pH, vl[2], vl[3]);
            }
        }
    }

    // ---- epilogue: divide by l, split to fp16 hi/lo, write [b,s,h*64+d] ----
    float inv0 = 1.0f / l0, inv1 = 1.0f / l1;
    const size_t rA = (size_t)(b*SEQ + q0 + w*16 + r4) * DMODEL + h*DHEAD + (l & 3) * 2;
    const size_t rB = rA + 8 * DMODEL;
#pragma unroll
    for (int j = 0; j < 8; j++) {
        uint32_t h0, l0w, h1, l1w;
        split2h(oacc[j][0] * inv0, oacc[j][1] * inv0, h0, l0w);
        split2h(oacc[j][2] * inv1, oacc[j][3] * inv1, h1, l1w);
        *(uint32_t*)(Oh + rA + j*8) = h0;
        *(uint32_t*)(Ol + rA + j*8) = l0w;
        *(uint32_t*)(Oh + rB + j*8) = h1;
        *(uint32_t*)(Ol + rB + j*8) = l1w;
    }
}

// =========================== launch ========================================
extern "C" void kernel_launch(void* const* d_in, const int* in_sizes, int n_in,
                              void* d_out, int out_size)
{
    (void)in_sizes; (void)n_in; (void)out_size;

    const float* qx = (const float*)d_in[0];
    const float* kx = (const float*)d_in[1];
    const float* vx = (const float*)d_in[2];
    const float* Wq = (const float*)d_in[3];
    const float* bq = (const float*)d_in[4];
    const float* Wk = (const float*)d_in[5];
    const float* bk = (const float*)d_in[6];
    const float* Wv = (const float*)d_in[7];
    const float* bv = (const float*)d_in[8];
    const float* Wo = (const float*)d_in[9];
    const float* bo = (const float*)d_in[10];
    float* out = (float*)d_out;

    float *gv;
    __half *aqh, *aql, *akh, *akl, *avh, *avl;
    __half *wqh, *wkh, *wvh;
    __half *qh, *ql, *kh, *vth, *vtl;
    cudaGetSymbolAddress((void**)&gv,  g_v);
    cudaGetSymbolAddress((void**)&aqh, g_aqh);
    cudaGetSymbolAddress((void**)&aql, g_aql);
    cudaGetSymbolAddress((void**)&akh, g_akh);
    cudaGetSymbolAddress((void**)&akl, g_akl);
    cudaGetSymbolAddress((void**)&avh, g_avh);
    cudaGetSymbolAddress((void**)&avl, g_avl);
    cudaGetSymbolAddress((void**)&wqh, g_wqh);
    cudaGetSymbolAddress((void**)&wkh, g_wkh);
    cudaGetSymbolAddress((void**)&wvh, g_wvh);
    cudaGetSymbolAddress((void**)&qh,  g_qh);
    cudaGetSymbolAddress((void**)&ql,  g_ql);
    cudaGetSymbolAddress((void**)&kh,  g_kh);
    cudaGetSymbolAddress((void**)&vth, g_vth);
    cudaGetSymbolAddress((void**)&vtl, g_vtl);

    cudaFuncSetAttribute(gemm_mma_kernel,
                         cudaFuncAttributeMaxDynamicSharedMemorySize, GEMM_SMEM);
    cudaFuncSetAttribute(attn_mma_kernel,
                         cudaFuncAttributeMaxDynamicSharedMemorySize, ATTN_SMEM_B);

    const int n4 = MROWS * DMODEL / 4;

    // fused QKV conversions + projections
    split3_kernel<<<dim3(n4/256, 3), 256>>>(qx, kx, vx,
                                            aqh, aql, akh, akl, avh, avl, n4);
    wtsplit3_kernel<<<dim3(32, 32, 3), 256>>>(Wq, Wk, Wv, wqh, wkh, wvh);
    GemmJob jq = {aqh, aql, wqh, bq, nullptr, qh, ql, 2};
    GemmJob jk = {akh, akl, wkh, bk, nullptr, kh, nullptr, 3};
    GemmJob jv = {avh, avl, wvh, bv, gv, nullptr, nullptr, 0};
    gemm_mma_kernel<<<dim3(8, 32, 3), 256, GEMM_SMEM>>>(jq, jk, jv);
    vtsplit_kernel<<<dim3(SEQ/32, DMODEL/32, BATCH), 256>>>(gv, vth, vtl);

    // attention -> ctx fp16 hi/lo straight into final-GEMM input buffers
    attn_mma_kernel<<<dim3(SEQ/BQ, NH, BATCH), 256, ATTN_SMEM_B>>>(
        qh, ql, kh, vth, vtl, aqh, aql);

    // output projection (reuse wq buffer for Wo)
    wtsplit3_kernel<<<dim3(32, 32, 1), 256>>>(Wo, Wo, Wo, wqh, wkh, wvh);
    GemmJob jo = {aqh, aql, wqh, bo, out, nullptr, nullptr, 0};
    gemm_mma_kernel<<<dim3(8, 32, 1), 256, GEMM_SMEM>>>(jo, jo, jo);
}

// round 15
// speedup vs baseline: 1.1869x; 1.1869x over previous
#include <cuda_runtime.h>
#include <cuda_bf16.h>
#include <cuda_fp16.h>
#include <cstdint>
#include <math.h>

#define BATCH 2
#define SEQ   2048
#define NH    16
#define DHEAD 64
#define DMODEL 1024
#define MROWS (BATCH*SEQ)   // 4096

// ---------------- scratch (device globals; no allocation allowed) ----------
__device__ float g_v[MROWS*DMODEL];
__device__ __half g_aqh[MROWS*DMODEL];
__device__ __half g_aql[MROWS*DMODEL];
__device__ __half g_akh[MROWS*DMODEL];
__device__ __half g_akl[MROWS*DMODEL];
__device__ __half g_avh[MROWS*DMODEL];
__device__ __half g_avl[MROWS*DMODEL];
__device__ __half g_wqh[DMODEL*DMODEL];
__device__ __half g_wkh[DMODEL*DMODEL];
__device__ __half g_wvh[DMODEL*DMODEL];
__device__ __half g_woh[DMODEL*DMODEL];
__device__ __half g_qh[MROWS*DMODEL];
__device__ __half g_ql[MROWS*DMODEL];
__device__ __half g_kh[MROWS*DMODEL];
__device__ __half g_vth[MROWS*DMODEL];      // V^T [b][h][d][s]

// ======================= helpers ===========================================
__device__ __forceinline__ uint32_t s2u(const void* p) {
    uint32_t a;
    asm("{ .reg .u64 t; cvta.to.shared.u64 t, %1; cvt.u32.u64 %0, t; }"
        : "=r"(a) : "l"(p));
    return a;
}
__device__ __forceinline__ void cp16(uint32_t d, const void* s) {
    asm volatile("cp.async.cg.shared.global [%0], [%1], 16;\n" :: "r"(d), "l"(s));
}
__device__ __forceinline__ void ldsm4(uint32_t* r, uint32_t addr) {
    asm volatile("ldmatrix.sync.aligned.m8n8.x4.shared.b16 {%0,%1,%2,%3}, [%4];"
        : "=r"(r[0]), "=r"(r[1]), "=r"(r[2]), "=r"(r[3]) : "r"(addr));
}
__device__ __forceinline__ void mma_f16(float* d, const uint32_t* a,
                                        uint32_t b0, uint32_t b1) {
    asm volatile(
        "mma.sync.aligned.m16n8k16.row.col.f32.f16.f16.f32 "
        "{%0,%1,%2,%3}, {%4,%5,%6,%7}, {%8,%9}, {%0,%1,%2,%3};"
        : "+f"(d[0]), "+f"(d[1]), "+f"(d[2]), "+f"(d[3])
        : "r"(a[0]), "r"(a[1]), "r"(a[2]), "r"(a[3]), "r"(b0), "r"(b1));
}
// fp16 split pair (x low, y high)
__device__ __forceinline__ void split2h(float x, float y,
                                        uint32_t& hi, uint32_t& lo) {
    __half2 H = __floats2half2_rn(x, y);
    __half2 L = __floats2half2_rn(x - __half2float(__low2half(H)),
                                  y - __half2float(__high2half(H)));
    hi = *(uint32_t*)&H;
    lo = *(uint32_t*)&L;
}
__device__ __forceinline__ uint32_t packh(float x, float y) {
    __half2 H = __floats2half2_rn(x, y);
    return *(uint32_t*)&H;
}

// ======================= split conversion kernels ==========================
__global__ __launch_bounds__(256)
void split3_kernel(const float* __restrict__ X0, const float* __restrict__ X1,
                   const float* __restrict__ X2,
                   __half* H0, __half* L0,
                   __half* H1, __half* L1,
                   __half* H2, __half* L2, int n4)
{
    int z = blockIdx.y;
    const float* X = z == 0 ? X0 : (z == 1 ? X1 : X2);
    __half* hi = z == 0 ? H0 : (z == 1 ? H1 : H2);
    __half* lo = z == 0 ? L0 : (z == 1 ? L1 : L2);
    int i = blockIdx.x * 256 + threadIdx.x;
    if (i >= n4) return;
    float4 v = ((const float4*)X)[i];
    uint32_t h0, l0, h1, l1;
    split2h(v.x, v.y, h0, l0);
    split2h(v.z, v.w, h1, l1);
    ((uint32_t*)hi)[2*i]   = h0;  ((uint32_t*)hi)[2*i+1] = h1;
    ((uint32_t*)lo)[2*i]   = l0;  ((uint32_t*)lo)[2*i+1] = l1;
}

// transpose: W[K,N] -> WT[N,K] as fp16 hi only (z selects matrix, 4 weights)
__global__ __launch_bounds__(256)
void wtsplit4_kernel(const float* __restrict__ W0, const float* __restrict__ W1,
                     const float* __restrict__ W2, const float* __restrict__ W3,
                     __half* H0, __half* H1, __half* H2, __half* H3)
{
    int z = blockIdx.z;
    const float* W = z == 0 ? W0 : (z == 1 ? W1 : (z == 2 ? W2 : W3));
    __half* wth = z == 0 ? H0 : (z == 1 ? H1 : (z == 2 ? H2 : H3));
    __shared__ float tile[32][33];
    int tx = threadIdx.x & 31, ty = threadIdx.x >> 5;  // 32x8
    int n0 = blockIdx.x * 32, k0 = blockIdx.y * 32;
#pragma unroll
    for (int i = 0; i < 4; i++)
        tile[ty + 8*i][tx] = W[(size_t)(k0 + ty + 8*i) * DMODEL + n0 + tx];
    __syncthreads();
#pragma unroll
    for (int i = 0; i < 4; i++) {
        float x = tile[tx][ty + 8*i];
        size_t o = (size_t)(n0 + ty + 8*i) * DMODEL + k0 + tx;
        wth[o] = __float2half_rn(x);
    }
}

// transpose V: V[b][s][h*64+d] -> Vt[b][h][d][s] fp16 hi only
__global__ __launch_bounds__(256)
void vtsplit_kernel(const float* __restrict__ V,
                    __half* __restrict__ vth)
{
    __shared__ float tile[32][33];
    int tx = threadIdx.x & 31, ty = threadIdx.x >> 5;  // 32x8
    int s0 = blockIdx.x * 32, d0 = blockIdx.y * 32, b = blockIdx.z;
#pragma unroll
    for (int i = 0; i < 4; i++)
        tile[ty + 8*i][tx] = V[((size_t)(b*SEQ) + s0 + ty + 8*i) * DMODEL + d0 + tx];
    __syncthreads();
#pragma unroll
    for (int i = 0; i < 4; i++) {
        int d = d0 + ty + 8*i;
        float x = tile[tx][ty + 8*i];
        int hh = d >> 6, dl = d & 63;
        size_t o = (((size_t)(b*NH + hh) * DHEAD + dl)) * SEQ + s0 + tx;
        vth[o] = __float2half_rn(x);
    }
}

// ======================= fp16 HMMA GEMM: C = A @ W^T + bias ================
// 2-pass: Ah*Wh + Al*Wh. W hi only. KC=64 (4 k-steps per stage). 2 CTAs/SM.
#define KC 64
#define ASTB 144                        // 64 halves (128B) + 16B pad
#define TILE_B (128*ASTB)               // 18432
#define STAGE_B (3*TILE_B)              // 55296 : Ah, Al, Wh
#define GEMM_SMEM (2*STAGE_B)           // 110592
#define NCH (DMODEL/KC)                 // 16

// out modes: 0 = fp32 C, 2 = fp16 hi/lo, 3 = fp16 hi only
struct GemmJob {
    const __half *Ah, *Al, *Bh;
    const float* bias;
    float* C;
    __half *Ch, *Cl;
    int mode;
};

__global__ __launch_bounds__(256, 2)
void gemm_mma_kernel(GemmJob j0, GemmJob j1, GemmJob j2)
{
    const GemmJob J = (blockIdx.z == 0) ? j0 : (blockIdx.z == 1 ? j1 : j2);
    extern __shared__ char smem[];
    const uint32_t sb = s2u(smem);
    const int t = threadIdx.x, w = t >> 5, l = t & 31;
    const int row0 = blockIdx.y * 128, col0 = blockIdx.x * 128;
    const int wm = (w & 1) * 64;
    const int wn = (w >> 1) * 32;

    float acc[4][4][4];
#pragma unroll
    for (int mt = 0; mt < 4; mt++)
#pragma unroll
        for (int nt = 0; nt < 4; nt++)
#pragma unroll
            for (int k = 0; k < 4; k++) acc[mt][nt][k] = 0.f;

    auto load_stage = [&](int c, int st) {
        const uint32_t base = sb + st * STAGE_B;
        const int kc = c * KC;
#pragma unroll
        for (int i = 0; i < 4; i++) {
            int u = t + i * 256;                 // 0..1023
            int r = u >> 3, j = u & 7;           // row, 16B chunk (8 per row)
            uint32_t dso = (uint32_t)(r * ASTB + j * 16);
            size_t ga = (size_t)(row0 + r) * DMODEL + kc + j * 8;
            size_t gb = (size_t)(col0 + r) * DMODEL + kc + j * 8;
            cp16(base + dso,              J.Ah + ga);
            cp16(base + TILE_B + dso,     J.Al + ga);
            cp16(base + 2*TILE_B + dso,   J.Bh + gb);
        }
        asm volatile("cp.async.commit_group;\n" ::: "memory");
    };

    load_stage(0, 0);

    // ldmatrix lane geometry
    const int aRow   = (l & 7) + ((l >> 3) & 1) * 8;
    const int aChunk = (l >> 4) * 16;
    const int bRow   = (l & 7) + ((l >> 4) << 3);
    const int bChunk = ((l >> 3) & 1) * 16;

    for (int c = 0; c < NCH; c++) {
        if (c + 1 < NCH) {
            load_stage(c + 1, (c + 1) & 1);
            asm volatile("cp.async.wait_group 1;\n" ::: "memory");
        } else {
            asm volatile("cp.async.wait_group 0;\n" ::: "memory");
        }
        __syncthreads();

        const uint32_t stg = sb + (c & 1) * STAGE_B;
        const uint32_t uAh = stg + (wm + aRow) * ASTB + aChunk;
        const uint32_t uAl = uAh + TILE_B;
        const uint32_t uBh = stg + 2*TILE_B + (wn + bRow) * ASTB + bChunk;

#pragma unroll
        for (int ks = 0; ks < 4; ks++) {
            const int kb = ks * 32;
            uint32_t aH[4][4], aL[4][4], bH[2][4];
#pragma unroll
            for (int mt = 0; mt < 4; mt++) {
                ldsm4(aH[mt], uAh + mt * (16*ASTB) + kb);
                ldsm4(aL[mt], uAl + mt * (16*ASTB) + kb);
            }
#pragma unroll
            for (int p = 0; p < 2; p++)
                ldsm4(bH[p], uBh + p * (16*ASTB) + kb);
#pragma unroll
            for (int mt = 0; mt < 4; mt++)
#pragma unroll
                for (int p = 0; p < 2; p++)
#pragma unroll
                    for (int hf = 0; hf < 2; hf++) {
                        int nt = p * 2 + hf;
                        uint32_t b0h = bH[p][2*hf], b1h = bH[p][2*hf+1];
                        mma_f16(acc[mt][nt], aH[mt], b0h, b1h);
                        mma_f16(acc[mt][nt], aL[mt], b0h, b1h);
                    }
        }
        __syncthreads();
    }

    const int ar = l >> 2;
#pragma unroll
    for (int mt = 0; mt < 4; mt++) {
        int gr0 = row0 + wm + mt * 16 + ar;
#pragma unroll
        for (int nt = 0; nt < 4; nt++) {
            int gc = col0 + wn + nt * 8 + (l & 3) * 2;
            float b0 = J.bias[gc], b1 = J.bias[gc + 1];
            float x0 = acc[mt][nt][0] + b0, y0 = acc[mt][nt][1] + b1;
            float x1 = acc[mt][nt][2] + b0, y1 = acc[mt][nt][3] + b1;
            size_t oA = (size_t)gr0 * DMODEL + gc;
            size_t oB = (size_t)(gr0 + 8) * DMODEL + gc;
            if (J.mode == 0) {
                *(float2*)(J.C + oA) = make_float2(x0, y0);
                *(float2*)(J.C + oB) = make_float2(x1, y1);
            } else if (J.mode == 2) {
                uint32_t h0, l0w, h1, l1w;
                split2h(x0, y0, h0, l0w);
                split2h(x1, y1, h1, l1w);
                ((uint32_t*)J.Ch)[oA >> 1] = h0;
                ((uint32_t*)J.Cl)[oA >> 1] = l0w;
                ((uint32_t*)J.Ch)[oB >> 1] = h1;
                ((uint32_t*)J.Cl)[oB >> 1] = l1w;
            } else {
                ((uint32_t*)J.Ch)[oA >> 1] = packh(x0, y0);
                ((uint32_t*)J.Ch)[oB >> 1] = packh(x1, y1);
            }
        }
    }
}

// ======================= fp16 HMMA flash attention =========================
// Q fp16 hi/lo (registers), K fp16 hi only, V fp16 hi only.
// QK 2-pass (Qh+Ql), PV 1-pass. 2 CTAs/SM (regs capped at 128).
#define BQ  128
#define BKV 64
#define NKV (SEQ/BKV)          // 32
#define STB 144                // smem row stride bytes (72 halves)
#define QTILE_B (128*STB)      // 18432
#define KTILE_B (64*STB)       // 9216
#define STAGE_AB (2*KTILE_B)   // 18432 : Kh, Vh
#define ATTN_SMEM_B (2*QTILE_B + 2*STAGE_AB)   // 73728

__global__ __launch_bounds__(256, 2)
void attn_mma_kernel(const __half* __restrict__ Qh,
                     const __half* __restrict__ Ql,
                     const __half* __restrict__ Kh,
                     const __half* __restrict__ Vth,
                     __half* __restrict__ Oh,
                     __half* __restrict__ Ol)
{
    extern __shared__ char smem[];
    const uint32_t sb = s2u(smem);
    const int t = threadIdx.x, w = t >> 5, l = t & 31;
    const int q0 = blockIdx.x * BQ;
    const int h  = blockIdx.y, b = blockIdx.z;
    const int r4 = l >> 2;

    // ---- prologue: Q hi/lo into smem ----
    {
        const __half* QhG = Qh + ((size_t)(b*SEQ + q0)) * DMODEL + h*DHEAD;
        const __half* QlG = Ql + ((size_t)(b*SEQ + q0)) * DMODEL + h*DHEAD;
#pragma unroll
        for (int i = 0; i < 8; i++) {
            int u = t + i * 256;               // 0..2047
            int tile = u >> 10, v = u & 1023;
            int row = v >> 3, ch = v & 7;
            uint32_t dst = sb + tile * QTILE_B + row * STB + ch * 16;
            const __half* src = (tile ? QlG : QhG) + (size_t)row * DMODEL + ch * 8;
            cp16(dst, src);
        }
    }
    auto load_kv = [&](int kvt, int st) {
        const uint32_t base = sb + 2*QTILE_B + st * STAGE_AB;
        int kv0 = kvt * BKV;
        const __half* KhG = Kh + ((size_t)(b*SEQ + kv0)) * DMODEL + h*DHEAD;
        const __half* VhG = Vth + ((size_t)(b*NH + h)) * DHEAD * SEQ + kv0;
#pragma unroll
        for (int i = 0; i < 4; i++) {
            int u = t + i * 256;               // 0..1023
            int tile = u >> 9, v = u & 511;
            int row = v >> 3, ch = v & 7;
            uint32_t dst = base + tile * KTILE_B + row * STB + ch * 16;
            const __half* src;
            if (tile == 0) src = KhG + (size_t)row * DMODEL + ch * 8;
            else           src = VhG + (size_t)row * SEQ + ch * 8;
            cp16(dst, src);
        }
        asm volatile("cp.async.commit_group;\n" ::: "memory");
    };
    load_kv(0, 0);
    asm volatile("cp.async.wait_group 0;\n" ::: "memory");
    __syncthreads();

    // ldmatrix lane geometry
    const int aRow   = (l & 7) + ((l >> 3) & 1) * 8;
    const int aChunk = (l >> 4) * 16;
    const int bRow   = (l & 7) + ((l >> 4) << 3);
    const int bChunk = ((l >> 3) & 1) * 16;

    // ---- Q fragments (held in registers for all kv tiles) ----
    uint32_t aH[4][4], aL[4][4];
    {
        const uint32_t qoff = sb + (w * 16 + aRow) * STB + aChunk;
#pragma unroll
        for (int s = 0; s < 4; s++) {
            ldsm4(aH[s], qoff + 32 * s);
            ldsm4(aL[s], qoff + QTILE_B + 32 * s);
        }
    }

    float m0 = -1e30f, m1 = -1e30f, l0 = 0.f, l1 = 0.f;
    float oacc[8][4];
#pragma unroll
    for (int j = 0; j < 8; j++)
#pragma unroll
        for (int k = 0; k < 4; k++) oacc[j][k] = 0.f;

    for (int kvt = 0; kvt < NKV; kvt++) {
        if (kvt + 1 < NKV) {
            load_kv(kvt + 1, (kvt + 1) & 1);
            asm volatile("cp.async.wait_group 1;\n" ::: "memory");
        } else {
            asm volatile("cp.async.wait_group 0;\n" ::: "memory");
        }
        __syncthreads();

        const uint32_t stg = sb + 2*QTILE_B + (kvt & 1) * STAGE_AB;
        const uint32_t uKh = stg + bRow * STB + bChunk;
        const uint32_t uVh = uKh + KTILE_B;

        // ---- scores: S = Q*K^T (2-pass: Qh*Kh + Ql*Kh) ----
        float sc[8][4];
#pragma unroll
        for (int j = 0; j < 8; j++)
#pragma unroll
            for (int k = 0; k < 4; k++) sc[j][k] = 0.f;

#pragma unroll
        for (int jp = 0; jp < 4; jp++) {
#pragma unroll
            for (int s = 0; s < 4; s++) {
                uint32_t kh[4];
                ldsm4(kh, uKh + jp * 2304 + 32 * s);
                mma_f16(sc[2*jp],   aH[s], kh[0], kh[1]);
                mma_f16(sc[2*jp],   aL[s], kh[0], kh[1]);
                mma_f16(sc[2*jp+1], aH[s], kh[2], kh[3]);
                mma_f16(sc[2*jp+1], aL[s], kh[2], kh[3]);
            }
        }
#pragma unroll
        for (int j = 0; j < 8; j++)
#pragma unroll
            for (int k = 0; k < 4; k++) sc[j][k] *= 0.125f;

        // ---- online softmax (rows r4 and r4+8 of this warp tile) ----
        float lm0 = -1e30f, lm1 = -1e30f;
#pragma unroll
        for (int j = 0; j < 8; j++) {
            lm0 = fmaxf(lm0, fmaxf(sc[j][0], sc[j][1]));
            lm1 = fmaxf(lm1, fmaxf(sc[j][2], sc[j][3]));
        }
        lm0 = fmaxf(lm0, __shfl_xor_sync(0xffffffffu, lm0, 1));
        lm0 = fmaxf(lm0, __shfl_xor_sync(0xffffffffu, lm0, 2));
        lm1 = fmaxf(lm1, __shfl_xor_sync(0xffffffffu, lm1, 1));
        lm1 = fmaxf(lm1, __shfl_xor_sync(0xffffffffu, lm1, 2));
        float mn0 = fmaxf(m0, lm0), mn1 = fmaxf(m1, lm1);
        float cf0 = __expf(m0 - mn0), cf1 = __expf(m1 - mn1);
        float rs0 = 0.f, rs1 = 0.f;
#pragma unroll
        for (int j = 0; j < 8; j++) {
            float p0 = __expf(sc[j][0] - mn0);
            float p1 = __expf(sc[j][1] - mn0);
            float p2 = __expf(sc[j][2] - mn1);
            float p3 = __expf(sc[j][3] - mn1);
            sc[j][0] = p0; sc[j][1] = p1; sc[j][2] = p2; sc[j][3] = p3;
            rs0 += p0 + p1;  rs1 += p2 + p3;
        }
        rs0 += __shfl_xor_sync(0xffffffffu, rs0, 1);
        rs0 += __shfl_xor_sync(0xffffffffu, rs0, 2);
        rs1 += __shfl_xor_sync(0xffffffffu, rs1, 1);
        rs1 += __shfl_xor_sync(0xffffffffu, rs1, 2);
        l0 = l0 * cf0 + rs0;  l1 = l1 * cf1 + rs1;
        m0 = mn0;  m1 = mn1;
#pragma unroll
        for (int j = 0; j < 8; j++) {
            oacc[j][0] *= cf0;  oacc[j][1] *= cf0;
            oacc[j][2] *= cf1;  oacc[j][3] *= cf1;
        }

        // ---- PV: ctx += P @ V (1-pass, V hi only), P plain fp16 ----
#pragma unroll
        for (int s = 0; s < 4; s++) {
            uint32_t pH[4];
            pH[0] = packh(sc[2*s][0],   sc[2*s][1]);
            pH[1] = packh(sc[2*s][2],   sc[2*s][3]);
            pH[2] = packh(sc[2*s+1][0], sc[2*s+1][1]);
            pH[3] = packh(sc[2*s+1][2], sc[2*s+1][3]);
#pragma unroll
            for (int jp = 0; jp < 4; jp++) {
                uint32_t vh[4];
                ldsm4(vh, uVh + jp * 2304 + 32 * s);
                mma_f16(oacc[2*jp],   pH, vh[0], vh[1]);
                mma_f16(oacc[2*jp+1], pH, vh[2], vh[3]);
            }
        }
        __syncthreads();
    }

    // ---- epilogue: divide by l, split to fp16 hi/lo, write [b,s,h*64+d] ----
    float inv0 = 1.0f / l0, inv1 = 1.0f / l1;
    const size_t rA = (size_t)(b*SEQ + q0 + w*16 + r4) * DMODEL + h*DHEAD + (l & 3) * 2;
    const size_t rB = rA + 8 * DMODEL;
#pragma unroll
    for (int j = 0; j < 8; j++) {
        uint32_t h0, l0w, h1, l1w;
        split2h(oacc[j][0] * inv0, oacc[j][1] * inv0, h0, l0w);
        split2h(oacc[j][2] * inv1, oacc[j][3] * inv1, h1, l1w);
        *(uint32_t*)(Oh + rA + j*8) = h0;
        *(uint32_t*)(Ol + rA + j*8) = l0w;
        *(uint32_t*)(Oh + rB + j*8) = h1;
        *(uint32_t*)(Ol + rB + j*8) = l1w;
    }
}

// =========================== launch ========================================
extern "C" void kernel_launch(void* const* d_in, const int* in_sizes, int n_in,
                              void* d_out, int out_size)
{
    (void)in_sizes; (void)n_in; (void)out_size;

    const float* qx = (const float*)d_in[0];
    const float* kx = (const float*)d_in[1];
    const float* vx = (const float*)d_in[2];
    const float* Wq = (const float*)d_in[3];
    const float* bq = (const float*)d_in[4];
    const float* Wk = (const float*)d_in[5];
    const float* bk = (const float*)d_in[6];
    const float* Wv = (const float*)d_in[7];
    const float* bv = (const float*)d_in[8];
    const float* Wo = (const float*)d_in[9];
    const float* bo = (const float*)d_in[10];
    float* out = (float*)d_out;

    float *gv;
    __half *aqh, *aql, *akh, *akl, *avh, *avl;
    __half *wqh, *wkh, *wvh, *woh;
    __half *qh, *ql, *kh, *vth;
    cudaGetSymbolAddress((void**)&gv,  g_v);
    cudaGetSymbolAddress((void**)&aqh, g_aqh);
    cudaGetSymbolAddress((void**)&aql, g_aql);
    cudaGetSymbolAddress((void**)&akh, g_akh);
    cudaGetSymbolAddress((void**)&akl, g_akl);
    cudaGetSymbolAddress((void**)&avh, g_avh);
    cudaGetSymbolAddress((void**)&avl, g_avl);
    cudaGetSymbolAddress((void**)&wqh, g_wqh);
    cudaGetSymbolAddress((void**)&wkh, g_wkh);
    cudaGetSymbolAddress((void**)&wvh, g_wvh);
    cudaGetSymbolAddress((void**)&woh, g_woh);
    cudaGetSymbolAddress((void**)&qh,  g_qh);
    cudaGetSymbolAddress((void**)&ql,  g_ql);
    cudaGetSymbolAddress((void**)&kh,  g_kh);
    cudaGetSymbolAddress((void**)&vth, g_vth);

    cudaFuncSetAttribute(gemm_mma_kernel,
                         cudaFuncAttributeMaxDynamicSharedMemorySize, GEMM_SMEM);
    cudaFuncSetAttribute(attn_mma_kernel,
                         cudaFuncAttributeMaxDynamicSharedMemorySize, ATTN_SMEM_B);

    const int n4 = MROWS * DMODEL / 4;

    // fused conversions: activations (3) + all four weights (1 launch)
    split3_kernel<<<dim3(n4/256, 3), 256>>>(qx, kx, vx,
                                            aqh, aql, akh, akl, avh, avl, n4);
    wtsplit4_kernel<<<dim3(32, 32, 4), 256>>>(Wq, Wk, Wv, Wo,
                                              wqh, wkh, wvh, woh);

    // fused QKV projections
    GemmJob jq = {aqh, aql, wqh, bq, nullptr, qh, ql, 2};
    GemmJob jk = {akh, akl, wkh, bk, nullptr, kh, nullptr, 3};
    GemmJob jv = {avh, avl, wvh, bv, gv, nullptr, nullptr, 0};
    gemm_mma_kernel<<<dim3(8, 32, 3), 256, GEMM_SMEM>>>(jq, jk, jv);
    vtsplit_kernel<<<dim3(SEQ/32, DMODEL/32, BATCH), 256>>>(gv, vth);

    // attention -> ctx fp16 hi/lo straight into final-GEMM input buffers
    attn_mma_kernel<<<dim3(SEQ/BQ, NH, BATCH), 256, ATTN_SMEM_B>>>(
        qh, ql, kh, vth, aqh, aql);

    // output projection
    GemmJob jo = {aqh, aql, woh, bo, out, nullptr, nullptr, 0};
    gemm_mma_kernel<<<dim3(8, 32, 1), 256, GEMM_SMEM>>>(jo, jo, jo);
}

// round 16
// speedup vs baseline: 1.1990x; 1.0102x over previous
#include <cuda_runtime.h>
#include <cuda_bf16.h>
#include <cuda_fp16.h>
#include <cstdint>
#include <math.h>

#define BATCH 2
#define SEQ   2048
#define NH    16
#define DHEAD 64
#define DMODEL 1024
#define MROWS (BATCH*SEQ)   // 4096

// ---------------- scratch (device globals; no allocation allowed) ----------
__device__ __half g_aqh[MROWS*DMODEL];
__device__ __half g_aql[MROWS*DMODEL];
__device__ __half g_akh[MROWS*DMODEL];
__device__ __half g_akl[MROWS*DMODEL];
__device__ __half g_avh[MROWS*DMODEL];
__device__ __half g_avl[MROWS*DMODEL];
__device__ __half g_wqh[DMODEL*DMODEL];
__device__ __half g_wkh[DMODEL*DMODEL];
__device__ __half g_wvh[DMODEL*DMODEL];
__device__ __half g_woh[DMODEL*DMODEL];
__device__ __half g_qh[MROWS*DMODEL];
__device__ __half g_ql[MROWS*DMODEL];
__device__ __half g_kh[MROWS*DMODEL];
__device__ __half g_vh[MROWS*DMODEL];       // V fp16 [b][s][h*64+d]

// ======================= helpers ===========================================
__device__ __forceinline__ uint32_t s2u(const void* p) {
    uint32_t a;
    asm("{ .reg .u64 t; cvta.to.shared.u64 t, %1; cvt.u32.u64 %0, t; }"
        : "=r"(a) : "l"(p));
    return a;
}
__device__ __forceinline__ void cp16(uint32_t d, const void* s) {
    asm volatile("cp.async.cg.shared.global [%0], [%1], 16;\n" :: "r"(d), "l"(s));
}
__device__ __forceinline__ void ldsm4(uint32_t* r, uint32_t addr) {
    asm volatile("ldmatrix.sync.aligned.m8n8.x4.shared.b16 {%0,%1,%2,%3}, [%4];"
        : "=r"(r[0]), "=r"(r[1]), "=r"(r[2]), "=r"(r[3]) : "r"(addr));
}
__device__ __forceinline__ void ldsm4t(uint32_t* r, uint32_t addr) {
    asm volatile("ldmatrix.sync.aligned.m8n8.x4.trans.shared.b16 {%0,%1,%2,%3}, [%4];"
        : "=r"(r[0]), "=r"(r[1]), "=r"(r[2]), "=r"(r[3]) : "r"(addr));
}
__device__ __forceinline__ void mma_f16(float* d, const uint32_t* a,
                                        uint32_t b0, uint32_t b1) {
    asm volatile(
        "mma.sync.aligned.m16n8k16.row.col.f32.f16.f16.f32 "
        "{%0,%1,%2,%3}, {%4,%5,%6,%7}, {%8,%9}, {%0,%1,%2,%3};"
        : "+f"(d[0]), "+f"(d[1]), "+f"(d[2]), "+f"(d[3])
        : "r"(a[0]), "r"(a[1]), "r"(a[2]), "r"(a[3]), "r"(b0), "r"(b1));
}
// fp16 split pair (x low, y high)
__device__ __forceinline__ void split2h(float x, float y,
                                        uint32_t& hi, uint32_t& lo) {
    __half2 H = __floats2half2_rn(x, y);
    __half2 L = __floats2half2_rn(x - __half2float(__low2half(H)),
                                  y - __half2float(__high2half(H)));
    hi = *(uint32_t*)&H;
    lo = *(uint32_t*)&L;
}
__device__ __forceinline__ uint32_t packh(float x, float y) {
    __half2 H = __floats2half2_rn(x, y);
    return *(uint32_t*)&H;
}

// ======================= split conversion kernels ==========================
// z==0 (qx) needs hi+lo; z==1,2 (kx,vx) feed 1-pass GEMMs -> hi only
__global__ __launch_bounds__(256)
void split3_kernel(const float* __restrict__ X0, const float* __restrict__ X1,
                   const float* __restrict__ X2,
                   __half* H0, __half* L0,
                   __half* H1, __half* L1,
                   __half* H2, __half* L2, int n4)
{
    int z = blockIdx.y;
    const float* X = z == 0 ? X0 : (z == 1 ? X1 : X2);
    __half* hi = z == 0 ? H0 : (z == 1 ? H1 : H2);
    __half* lo = z == 0 ? L0 : (z == 1 ? L1 : L2);
    int i = blockIdx.x * 256 + threadIdx.x;
    if (i >= n4) return;
    float4 v = ((const float4*)X)[i];
    uint32_t h0, l0, h1, l1;
    split2h(v.x, v.y, h0, l0);
    split2h(v.z, v.w, h1, l1);
    ((uint32_t*)hi)[2*i]   = h0;  ((uint32_t*)hi)[2*i+1] = h1;
    if (z == 0) {
        ((uint32_t*)lo)[2*i]   = l0;  ((uint32_t*)lo)[2*i+1] = l1;
    }
}

// transpose: W[K,N] -> WT[N,K] as fp16 hi only (z selects matrix, 4 weights)
__global__ __launch_bounds__(256)
void wtsplit4_kernel(const float* __restrict__ W0, const float* __restrict__ W1,
                     const float* __restrict__ W2, const float* __restrict__ W3,
                     __half* H0, __half* H1, __half* H2, __half* H3)
{
    int z = blockIdx.z;
    const float* W = z == 0 ? W0 : (z == 1 ? W1 : (z == 2 ? W2 : W3));
    __half* wth = z == 0 ? H0 : (z == 1 ? H1 : (z == 2 ? H2 : H3));
    __shared__ float tile[32][33];
    int tx = threadIdx.x & 31, ty = threadIdx.x >> 5;  // 32x8
    int n0 = blockIdx.x * 32, k0 = blockIdx.y * 32;
#pragma unroll
    for (int i = 0; i < 4; i++)
        tile[ty + 8*i][tx] = W[(size_t)(k0 + ty + 8*i) * DMODEL + n0 + tx];
    __syncthreads();
#pragma unroll
    for (int i = 0; i < 4; i++) {
        float x = tile[tx][ty + 8*i];
        size_t o = (size_t)(n0 + ty + 8*i) * DMODEL + k0 + tx;
        wth[o] = __float2half_rn(x);
    }
}

// ======================= fp16 HMMA GEMM: C = A @ W^T + bias ================
// npass=2: Ah*Wh + Al*Wh ; npass=1: Ah*Wh only. KC=64. 2 CTAs/SM.
#define KC 64
#define ASTB 144                        // 64 halves (128B) + 16B pad
#define TILE_B (128*ASTB)               // 18432
#define STAGE_B (3*TILE_B)              // 55296 : Ah, Al, Wh
#define GEMM_SMEM (2*STAGE_B)           // 110592
#define NCH (DMODEL/KC)                 // 16

// out modes: 0 = fp32 C, 2 = fp16 hi/lo, 3 = fp16 hi only
struct GemmJob {
    const __half *Ah, *Al, *Bh;
    const float* bias;
    float* C;
    __half *Ch, *Cl;
    int mode;
    int npass;
};

__global__ __launch_bounds__(256, 2)
void gemm_mma_kernel(GemmJob j0, GemmJob j1, GemmJob j2)
{
    const GemmJob J = (blockIdx.z == 0) ? j0 : (blockIdx.z == 1 ? j1 : j2);
    extern __shared__ char smem[];
    const uint32_t sb = s2u(smem);
    const int t = threadIdx.x, w = t >> 5, l = t & 31;
    const int row0 = blockIdx.y * 128, col0 = blockIdx.x * 128;
    const int wm = (w & 1) * 64;
    const int wn = (w >> 1) * 32;

    float acc[4][4][4];
#pragma unroll
    for (int mt = 0; mt < 4; mt++)
#pragma unroll
        for (int nt = 0; nt < 4; nt++)
#pragma unroll
            for (int k = 0; k < 4; k++) acc[mt][nt][k] = 0.f;

    auto load_stage = [&](int c, int st) {
        const uint32_t base = sb + st * STAGE_B;
        const int kc = c * KC;
#pragma unroll
        for (int i = 0; i < 4; i++) {
            int u = t + i * 256;                 // 0..1023
            int r = u >> 3, j = u & 7;           // row, 16B chunk (8 per row)
            uint32_t dso = (uint32_t)(r * ASTB + j * 16);
            size_t ga = (size_t)(row0 + r) * DMODEL + kc + j * 8;
            size_t gb = (size_t)(col0 + r) * DMODEL + kc + j * 8;
            cp16(base + dso,              J.Ah + ga);
            if (J.npass == 2) cp16(base + TILE_B + dso, J.Al + ga);
            cp16(base + 2*TILE_B + dso,   J.Bh + gb);
        }
        asm volatile("cp.async.commit_group;\n" ::: "memory");
    };

    load_stage(0, 0);

    // ldmatrix lane geometry
    const int aRow   = (l & 7) + ((l >> 3) & 1) * 8;
    const int aChunk = (l >> 4) * 16;
    const int bRow   = (l & 7) + ((l >> 4) << 3);
    const int bChunk = ((l >> 3) & 1) * 16;

    for (int c = 0; c < NCH; c++) {
        if (c + 1 < NCH) {
            load_stage(c + 1, (c + 1) & 1);
            asm volatile("cp.async.wait_group 1;\n" ::: "memory");
        } else {
            asm volatile("cp.async.wait_group 0;\n" ::: "memory");
        }
        __syncthreads();

        const uint32_t stg = sb + (c & 1) * STAGE_B;
        const uint32_t uAh = stg + (wm + aRow) * ASTB + aChunk;
        const uint32_t uAl = uAh + TILE_B;
        const uint32_t uBh = stg + 2*TILE_B + (wn + bRow) * ASTB + bChunk;

#pragma unroll
        for (int ks = 0; ks < 4; ks++) {
            const int kb = ks * 32;
            uint32_t aH[4][4], aL[4][4], bH[2][4];
#pragma unroll
            for (int mt = 0; mt < 4; mt++) {
                ldsm4(aH[mt], uAh + mt * (16*ASTB) + kb);
                if (J.npass == 2) ldsm4(aL[mt], uAl + mt * (16*ASTB) + kb);
            }
#pragma unroll
            for (int p = 0; p < 2; p++)
                ldsm4(bH[p], uBh + p * (16*ASTB) + kb);
#pragma unroll
            for (int mt = 0; mt < 4; mt++)
#pragma unroll
                for (int p = 0; p < 2; p++)
#pragma unroll
                    for (int hf = 0; hf < 2; hf++) {
                        int nt = p * 2 + hf;
                        uint32_t b0h = bH[p][2*hf], b1h = bH[p][2*hf+1];
                        mma_f16(acc[mt][nt], aH[mt], b0h, b1h);
                        if (J.npass == 2) mma_f16(acc[mt][nt], aL[mt], b0h, b1h);
                    }
        }
        __syncthreads();
    }

    const int ar = l >> 2;
#pragma unroll
    for (int mt = 0; mt < 4; mt++) {
        int gr0 = row0 + wm + mt * 16 + ar;
#pragma unroll
        for (int nt = 0; nt < 4; nt++) {
            int gc = col0 + wn + nt * 8 + (l & 3) * 2;
            float b0 = J.bias[gc], b1 = J.bias[gc + 1];
            float x0 = acc[mt][nt][0] + b0, y0 = acc[mt][nt][1] + b1;
            float x1 = acc[mt][nt][2] + b0, y1 = acc[mt][nt][3] + b1;
            size_t oA = (size_t)gr0 * DMODEL + gc;
            size_t oB = (size_t)(gr0 + 8) * DMODEL + gc;
            if (J.mode == 0) {
                *(float2*)(J.C + oA) = make_float2(x0, y0);
                *(float2*)(J.C + oB) = make_float2(x1, y1);
            } else if (J.mode == 2) {
                uint32_t h0, l0w, h1, l1w;
                split2h(x0, y0, h0, l0w);
                split2h(x1, y1, h1, l1w);
                ((uint32_t*)J.Ch)[oA >> 1] = h0;
                ((uint32_t*)J.Cl)[oA >> 1] = l0w;
                ((uint32_t*)J.Ch)[oB >> 1] = h1;
                ((uint32_t*)J.Cl)[oB >> 1] = l1w;
            } else {
                ((uint32_t*)J.Ch)[oA >> 1] = packh(x0, y0);
                ((uint32_t*)J.Ch)[oB >> 1] = packh(x1, y1);
            }
        }
    }
}

// ======================= fp16 HMMA flash attention =========================
// Q fp16 hi/lo (registers), K fp16 hi, V fp16 hi in natural [b,s,D] layout
// (PV B-operand via ldmatrix.trans). QK 2-pass, PV 1-pass. 2 CTAs/SM.
#define BQ  128
#define BKV 64
#define NKV (SEQ/BKV)          // 32
#define STB 144                // smem row stride bytes (72 halves)
#define QTILE_B (128*STB)      // 18432
#define KTILE_B (64*STB)       // 9216
#define STAGE_AB (2*KTILE_B)   // 18432 : Kh, Vh
#define ATTN_SMEM_B (2*QTILE_B + 2*STAGE_AB)   // 73728

__global__ __launch_bounds__(256, 2)
void attn_mma_kernel(const __half* __restrict__ Qh,
                     const __half* __restrict__ Ql,
                     const __half* __restrict__ Kh,
                     const __half* __restrict__ Vh,
                     __half* __restrict__ Oh,
                     __half* __restrict__ Ol)
{
    extern __shared__ char smem[];
    const uint32_t sb = s2u(smem);
    const int t = threadIdx.x, w = t >> 5, l = t & 31;
    const int q0 = blockIdx.x * BQ;
    const int h  = blockIdx.y, b = blockIdx.z;
    const int r4 = l >> 2;

    // ---- prologue: Q hi/lo into smem ----
    {
        const __half* QhG = Qh + ((size_t)(b*SEQ + q0)) * DMODEL + h*DHEAD;
        const __half* QlG = Ql + ((size_t)(b*SEQ + q0)) * DMODEL + h*DHEAD;
#pragma unroll
        for (int i = 0; i < 8; i++) {
            int u = t + i * 256;               // 0..2047
            int tile = u >> 10, v = u & 1023;
            int row = v >> 3, ch = v & 7;
            uint32_t dst = sb + tile * QTILE_B + row * STB + ch * 16;
            const __half* src = (tile ? QlG : QhG) + (size_t)row * DMODEL + ch * 8;
            cp16(dst, src);
        }
    }
    auto load_kv = [&](int kvt, int st) {
        const uint32_t base = sb + 2*QTILE_B + st * STAGE_AB;
        int kv0 = kvt * BKV;
        const __half* KhG = Kh + ((size_t)(b*SEQ + kv0)) * DMODEL + h*DHEAD;
        const __half* VhG = Vh + ((size_t)(b*SEQ + kv0)) * DMODEL + h*DHEAD;
#pragma unroll
        for (int i = 0; i < 4; i++) {
            int u = t + i * 256;               // 0..1023
            int tile = u >> 9, v = u & 511;
            int row = v >> 3, ch = v & 7;
            uint32_t dst = base + tile * KTILE_B + row * STB + ch * 16;
            const __half* src = (tile == 0 ? KhG : VhG) + (size_t)row * DMODEL + ch * 8;
            cp16(dst, src);
        }
        asm volatile("cp.async.commit_group;\n" ::: "memory");
    };
    load_kv(0, 0);
    asm volatile("cp.async.wait_group 0;\n" ::: "memory");
    __syncthreads();

    // ldmatrix lane geometry
    const int aRow   = (l & 7) + ((l >> 3) & 1) * 8;
    const int aChunk = (l >> 4) * 16;
    const int bRow   = (l & 7) + ((l >> 4) << 3);
    const int bChunk = ((l >> 3) & 1) * 16;

    // ---- Q fragments (held in registers for all kv tiles) ----
    uint32_t aH[4][4], aL[4][4];
    {
        const uint32_t qoff = sb + (w * 16 + aRow) * STB + aChunk;
#pragma unroll
        for (int s = 0; s < 4; s++) {
            ldsm4(aH[s], qoff + 32 * s);
            ldsm4(aL[s], qoff + QTILE_B + 32 * s);
        }
    }

    float m0 = -1e30f, m1 = -1e30f, l0 = 0.f, l1 = 0.f;
    float oacc[8][4];
#pragma unroll
    for (int j = 0; j < 8; j++)
#pragma unroll
        for (int k = 0; k < 4; k++) oacc[j][k] = 0.f;

    for (int kvt = 0; kvt < NKV; kvt++) {
        if (kvt + 1 < NKV) {
            load_kv(kvt + 1, (kvt + 1) & 1);
            asm volatile("cp.async.wait_group 1;\n" ::: "memory");
        } else {
            asm volatile("cp.async.wait_group 0;\n" ::: "memory");
        }
        __syncthreads();

        const uint32_t stg = sb + 2*QTILE_B + (kvt & 1) * STAGE_AB;
        const uint32_t uKh = stg + bRow * STB + bChunk;
        // trans-V: rows = kv (aRow pattern), 16B col chunk = d (aChunk)
        const uint32_t uVt = stg + KTILE_B + aRow * STB + aChunk;

        // ---- scores: S = Q*K^T (2-pass: Qh*Kh + Ql*Kh) ----
        float sc[8][4];
#pragma unroll
        for (int j = 0; j < 8; j++)
#pragma unroll
            for (int k = 0; k < 4; k++) sc[j][k] = 0.f;

#pragma unroll
        for (int jp = 0; jp < 4; jp++) {
#pragma unroll
            for (int s = 0; s < 4; s++) {
                uint32_t kh[4];
                ldsm4(kh, uKh + jp * 2304 + 32 * s);
                mma_f16(sc[2*jp],   aH[s], kh[0], kh[1]);
                mma_f16(sc[2*jp],   aL[s], kh[0], kh[1]);
                mma_f16(sc[2*jp+1], aH[s], kh[2], kh[3]);
                mma_f16(sc[2*jp+1], aL[s], kh[2], kh[3]);
            }
        }
#pragma unroll
        for (int j = 0; j < 8; j++)
#pragma unroll
            for (int k = 0; k < 4; k++) sc[j][k] *= 0.125f;

        // ---- online softmax (rows r4 and r4+8 of this warp tile) ----
        float lm0 = -1e30f, lm1 = -1e30f;
#pragma unroll
        for (int j = 0; j < 8; j++) {
            lm0 = fmaxf(lm0, fmaxf(sc[j][0], sc[j][1]));
            lm1 = fmaxf(lm1, fmaxf(sc[j][2], sc[j][3]));
        }
        lm0 = fmaxf(lm0, __shfl_xor_sync(0xffffffffu, lm0, 1));
        lm0 = fmaxf(lm0, __shfl_xor_sync(0xffffffffu, lm0, 2));
        lm1 = fmaxf(lm1, __shfl_xor_sync(0xffffffffu, lm1, 1));
        lm1 = fmaxf(lm1, __shfl_xor_sync(0xffffffffu, lm1, 2));
        float mn0 = fmaxf(m0, lm0), mn1 = fmaxf(m1, lm1);
        float cf0 = __expf(m0 - mn0), cf1 = __expf(m1 - mn1);
        float rs0 = 0.f, rs1 = 0.f;
#pragma unroll
        for (int j = 0; j < 8; j++) {
            float p0 = __expf(sc[j][0] - mn0);
            float p1 = __expf(sc[j][1] - mn0);
            float p2 = __expf(sc[j][2] - mn1);
            float p3 = __expf(sc[j][3] - mn1);
            sc[j][0] = p0; sc[j][1] = p1; sc[j][2] = p2; sc[j][3] = p3;
            rs0 += p0 + p1;  rs1 += p2 + p3;
        }
        rs0 += __shfl_xor_sync(0xffffffffu, rs0, 1);
        rs0 += __shfl_xor_sync(0xffffffffu, rs0, 2);
        rs1 += __shfl_xor_sync(0xffffffffu, rs1, 1);
        rs1 += __shfl_xor_sync(0xffffffffu, rs1, 2);
        l0 = l0 * cf0 + rs0;  l1 = l1 * cf1 + rs1;
        m0 = mn0;  m1 = mn1;
#pragma unroll
        for (int j = 0; j < 8; j++) {
            oacc[j][0] *= cf0;  oacc[j][1] *= cf0;
            oacc[j][2] *= cf1;  oacc[j][3] *= cf1;
        }

        // ---- PV: ctx += P @ V (1-pass, V via trans ldmatrix), P fp16 ----
#pragma unroll
        for (int s = 0; s < 4; s++) {
            uint32_t pH[4];
            pH[0] = packh(sc[2*s][0],   sc[2*s][1]);
            pH[1] = packh(sc[2*s][2],   sc[2*s][3]);
            pH[2] = packh(sc[2*s+1][0], sc[2*s+1][1]);
            pH[3] = packh(sc[2*s+1][2], sc[2*s+1][3]);
#pragma unroll
            for (int jp = 0; jp < 4; jp++) {
                uint32_t vh[4];
                ldsm4t(vh, uVt + s * (16*STB) + jp * 32);
                mma_f16(oacc[2*jp],   pH, vh[0], vh[1]);
                mma_f16(oacc[2*jp+1], pH, vh[2], vh[3]);
            }
        }
        __syncthreads();
    }

    // ---- epilogue: divide by l, split to fp16 hi/lo, write [b,s,h*64+d] ----
    float inv0 = 1.0f / l0, inv1 = 1.0f / l1;
    const size_t rA = (size_t)(b*SEQ + q0 + w*16 + r4) * DMODEL + h*DHEAD + (l & 3) * 2;
    const size_t rB = rA + 8 * DMODEL;
#pragma unroll
    for (int j = 0; j < 8; j++) {
        uint32_t h0, l0w, h1, l1w;
        split2h(oacc[j][0] * inv0, oacc[j][1] * inv0, h0, l0w);
        split2h(oacc[j][2] * inv1, oacc[j][3] * inv1, h1, l1w);
        *(uint32_t*)(Oh + rA + j*8) = h0;
        *(uint32_t*)(Ol + rA + j*8) = l0w;
        *(uint32_t*)(Oh + rB + j*8) = h1;
        *(uint32_t*)(Ol + rB + j*8) = l1w;
    }
}

// =========================== launch ========================================
extern "C" void kernel_launch(void* const* d_in, const int* in_sizes, int n_in,
                              void* d_out, int out_size)
{
    (void)in_sizes; (void)n_in; (void)out_size;

    const float* qx = (const float*)d_in[0];
    const float* kx = (const float*)d_in[1];
    const float* vx = (const float*)d_in[2];
    const float* Wq = (const float*)d_in[3];
    const float* bq = (const float*)d_in[4];
    const float* Wk = (const float*)d_in[5];
    const float* bk = (const float*)d_in[6];
    const float* Wv = (const float*)d_in[7];
    const float* bv = (const float*)d_in[8];
    const float* Wo = (const float*)d_in[9];
    const float* bo = (const float*)d_in[10];
    float* out = (float*)d_out;

    __half *aqh, *aql, *akh, *akl, *avh, *avl;
    __half *wqh, *wkh, *wvh, *woh;
    __half *qh, *ql, *kh, *vh;
    cudaGetSymbolAddress((void**)&aqh, g_aqh);
    cudaGetSymbolAddress((void**)&aql, g_aql);
    cudaGetSymbolAddress((void**)&akh, g_akh);
    cudaGetSymbolAddress((void**)&akl, g_akl);
    cudaGetSymbolAddress((void**)&avh, g_avh);
    cudaGetSymbolAddress((void**)&avl, g_avl);
    cudaGetSymbolAddress((void**)&wqh, g_wqh);
    cudaGetSymbolAddress((void**)&wkh, g_wkh);
    cudaGetSymbolAddress((void**)&wvh, g_wvh);
    cudaGetSymbolAddress((void**)&woh, g_woh);
    cudaGetSymbolAddress((void**)&qh,  g_qh);
    cudaGetSymbolAddress((void**)&ql,  g_ql);
    cudaGetSymbolAddress((void**)&kh,  g_kh);
    cudaGetSymbolAddress((void**)&vh,  g_vh);

    cudaFuncSetAttribute(gemm_mma_kernel,
                         cudaFuncAttributeMaxDynamicSharedMemorySize, GEMM_SMEM);
    cudaFuncSetAttribute(attn_mma_kernel,
                         cudaFuncAttributeMaxDynamicSharedMemorySize, ATTN_SMEM_B);

    const int n4 = MROWS * DMODEL / 4;

    // fused conversions: activations (3) + all four weights (1 launch)
    split3_kernel<<<dim3(n4/256, 3), 256>>>(qx, kx, vx,
                                            aqh, aql, akh, akl, avh, avl, n4);
    wtsplit4_kernel<<<dim3(32, 32, 4), 256>>>(Wq, Wk, Wv, Wo,
                                              wqh, wkh, wvh, woh);

    // fused QKV projections (Q 2-pass fp16 hi/lo; K,V 1-pass fp16 hi)
    GemmJob jq = {aqh, aql, wqh, bq, nullptr, qh, ql, 2, 2};
    GemmJob jk = {akh, akl, wkh, bk, nullptr, kh, nullptr, 3, 1};
    GemmJob jv = {avh, avl, wvh, bv, nullptr, vh, nullptr, 3, 1};
    gemm_mma_kernel<<<dim3(8, 32, 3), 256, GEMM_SMEM>>>(jq, jk, jv);

    // attention -> ctx fp16 hi/lo straight into final-GEMM input buffers
    attn_mma_kernel<<<dim3(SEQ/BQ, NH, BATCH), 256, ATTN_SMEM_B>>>(
        qh, ql, kh, vh, aqh, aql);

    // output projection (2-pass, fp32 out)
    GemmJob jo = {aqh, aql, woh, bo, out, nullptr, nullptr, 0, 2};
    gemm_mma_kernel<<<dim3(8, 32, 1), 256, GEMM_SMEM>>>(jo, jo, jo);
}

// round 17
// speedup vs baseline: 1.3205x; 1.1014x over previous
#include <cuda_runtime.h>
#include <cuda_bf16.h>
#include <cuda_fp16.h>
#include <cstdint>
#include <math.h>

#define BATCH 2
#define SEQ   2048
#define NH    16
#define DHEAD 64
#define DMODEL 1024
#define MROWS (BATCH*SEQ)   // 4096

// ---------------- scratch (device globals; no allocation allowed) ----------
__device__ __half g_aqh[MROWS*DMODEL];
__device__ __half g_aql[MROWS*DMODEL];
__device__ __half g_akh[MROWS*DMODEL];
__device__ __half g_avh[MROWS*DMODEL];
__device__ __half g_wqh[DMODEL*DMODEL];
__device__ __half g_wkh[DMODEL*DMODEL];
__device__ __half g_wvh[DMODEL*DMODEL];
__device__ __half g_woh[DMODEL*DMODEL];
__device__ __half g_qh[MROWS*DMODEL];
__device__ __half g_kh[MROWS*DMODEL];
__device__ __half g_vh[MROWS*DMODEL];       // V fp16 [b][s][h*64+d]

// ======================= helpers ===========================================
__device__ __forceinline__ uint32_t s2u(const void* p) {
    uint32_t a;
    asm("{ .reg .u64 t; cvta.to.shared.u64 t, %1; cvt.u32.u64 %0, t; }"
        : "=r"(a) : "l"(p));
    return a;
}
__device__ __forceinline__ void cp16(uint32_t d, const void* s) {
    asm volatile("cp.async.cg.shared.global [%0], [%1], 16;\n" :: "r"(d), "l"(s));
}
__device__ __forceinline__ void ldsm4(uint32_t* r, uint32_t addr) {
    asm volatile("ldmatrix.sync.aligned.m8n8.x4.shared.b16 {%0,%1,%2,%3}, [%4];"
        : "=r"(r[0]), "=r"(r[1]), "=r"(r[2]), "=r"(r[3]) : "r"(addr));
}
__device__ __forceinline__ void ldsm4t(uint32_t* r, uint32_t addr) {
    asm volatile("ldmatrix.sync.aligned.m8n8.x4.trans.shared.b16 {%0,%1,%2,%3}, [%4];"
        : "=r"(r[0]), "=r"(r[1]), "=r"(r[2]), "=r"(r[3]) : "r"(addr));
}
__device__ __forceinline__ void mma_f16(float* d, const uint32_t* a,
                                        uint32_t b0, uint32_t b1) {
    asm volatile(
        "mma.sync.aligned.m16n8k16.row.col.f32.f16.f16.f32 "
        "{%0,%1,%2,%3}, {%4,%5,%6,%7}, {%8,%9}, {%0,%1,%2,%3};"
        : "+f"(d[0]), "+f"(d[1]), "+f"(d[2]), "+f"(d[3])
        : "r"(a[0]), "r"(a[1]), "r"(a[2]), "r"(a[3]), "r"(b0), "r"(b1));
}
// fp16 split pair (x low, y high)
__device__ __forceinline__ void split2h(float x, float y,
                                        uint32_t& hi, uint32_t& lo) {
    __half2 H = __floats2half2_rn(x, y);
    __half2 L = __floats2half2_rn(x - __half2float(__low2half(H)),
                                  y - __half2float(__high2half(H)));
    hi = *(uint32_t*)&H;
    lo = *(uint32_t*)&L;
}
__device__ __forceinline__ uint32_t packh(float x, float y) {
    __half2 H = __floats2half2_rn(x, y);
    return *(uint32_t*)&H;
}

// ======================= split conversion kernels ==========================
// z==0 (qx) needs hi+lo (2-pass Q GEMM); z==1,2 (kx,vx) hi only
__global__ __launch_bounds__(256)
void split3_kernel(const float* __restrict__ X0, const float* __restrict__ X1,
                   const float* __restrict__ X2,
                   __half* H0, __half* L0,
                   __half* H1, __half* H2, int n4)
{
    int z = blockIdx.y;
    const float* X = z == 0 ? X0 : (z == 1 ? X1 : X2);
    __half* hi = z == 0 ? H0 : (z == 1 ? H1 : H2);
    int i = blockIdx.x * 256 + threadIdx.x;
    if (i >= n4) return;
    float4 v = ((const float4*)X)[i];
    uint32_t h0, l0, h1, l1;
    split2h(v.x, v.y, h0, l0);
    split2h(v.z, v.w, h1, l1);
    ((uint32_t*)hi)[2*i]   = h0;  ((uint32_t*)hi)[2*i+1] = h1;
    if (z == 0) {
        ((uint32_t*)L0)[2*i]   = l0;  ((uint32_t*)L0)[2*i+1] = l1;
    }
}

// transpose: W[K,N] -> WT[N,K] as fp16 hi only (z selects matrix, 4 weights)
__global__ __launch_bounds__(256)
void wtsplit4_kernel(const float* __restrict__ W0, const float* __restrict__ W1,
                     const float* __restrict__ W2, const float* __restrict__ W3,
                     __half* H0, __half* H1, __half* H2, __half* H3)
{
    int z = blockIdx.z;
    const float* W = z == 0 ? W0 : (z == 1 ? W1 : (z == 2 ? W2 : W3));
    __half* wth = z == 0 ? H0 : (z == 1 ? H1 : (z == 2 ? H2 : H3));
    __shared__ float tile[32][33];
    int tx = threadIdx.x & 31, ty = threadIdx.x >> 5;  // 32x8
    int n0 = blockIdx.x * 32, k0 = blockIdx.y * 32;
#pragma unroll
    for (int i = 0; i < 4; i++)
        tile[ty + 8*i][tx] = W[(size_t)(k0 + ty + 8*i) * DMODEL + n0 + tx];
    __syncthreads();
#pragma unroll
    for (int i = 0; i < 4; i++) {
        float x = tile[tx][ty + 8*i];
        size_t o = (size_t)(n0 + ty + 8*i) * DMODEL + k0 + tx;
        wth[o] = __float2half_rn(x);
    }
}

// ======================= fp16 HMMA GEMM: C = A @ W^T + bias ================
// npass=2: Ah*Wh + Al*Wh ; npass=1: Ah*Wh only. KC=64. 2 CTAs/SM.
#define KC 64
#define ASTB 144                        // 64 halves (128B) + 16B pad
#define TILE_B (128*ASTB)               // 18432
#define STAGE_B (3*TILE_B)              // 55296 : Ah, Al, Wh
#define GEMM_SMEM (2*STAGE_B)           // 110592
#define NCH (DMODEL/KC)                 // 16

// out modes: 0 = fp32 C, 2 = fp16 hi/lo, 3 = fp16 hi only
struct GemmJob {
    const __half *Ah, *Al, *Bh;
    const float* bias;
    float* C;
    __half *Ch, *Cl;
    int mode;
    int npass;
};

__global__ __launch_bounds__(256, 2)
void gemm_mma_kernel(GemmJob j0, GemmJob j1, GemmJob j2)
{
    const GemmJob J = (blockIdx.z == 0) ? j0 : (blockIdx.z == 1 ? j1 : j2);
    extern __shared__ char smem[];
    const uint32_t sb = s2u(smem);
    const int t = threadIdx.x, w = t >> 5, l = t & 31;
    const int row0 = blockIdx.y * 128, col0 = blockIdx.x * 128;
    const int wm = (w & 1) * 64;
    const int wn = (w >> 1) * 32;

    float acc[4][4][4];
#pragma unroll
    for (int mt = 0; mt < 4; mt++)
#pragma unroll
        for (int nt = 0; nt < 4; nt++)
#pragma unroll
            for (int k = 0; k < 4; k++) acc[mt][nt][k] = 0.f;

    auto load_stage = [&](int c, int st) {
        const uint32_t base = sb + st * STAGE_B;
        const int kc = c * KC;
#pragma unroll
        for (int i = 0; i < 4; i++) {
            int u = t + i * 256;                 // 0..1023
            int r = u >> 3, j = u & 7;           // row, 16B chunk (8 per row)
            uint32_t dso = (uint32_t)(r * ASTB + j * 16);
            size_t ga = (size_t)(row0 + r) * DMODEL + kc + j * 8;
            size_t gb = (size_t)(col0 + r) * DMODEL + kc + j * 8;
            cp16(base + dso,              J.Ah + ga);
            if (J.npass == 2) cp16(base + TILE_B + dso, J.Al + ga);
            cp16(base + 2*TILE_B + dso,   J.Bh + gb);
        }
        asm volatile("cp.async.commit_group;\n" ::: "memory");
    };

    load_stage(0, 0);

    // ldmatrix lane geometry
    const int aRow   = (l & 7) + ((l >> 3) & 1) * 8;
    const int aChunk = (l >> 4) * 16;
    const int bRow   = (l & 7) + ((l >> 4) << 3);
    const int bChunk = ((l >> 3) & 1) * 16;

    for (int c = 0; c < NCH; c++) {
        if (c + 1 < NCH) {
            load_stage(c + 1, (c + 1) & 1);
            asm volatile("cp.async.wait_group 1;\n" ::: "memory");
        } else {
            asm volatile("cp.async.wait_group 0;\n" ::: "memory");
        }
        __syncthreads();

        const uint32_t stg = sb + (c & 1) * STAGE_B;
        const uint32_t uAh = stg + (wm + aRow) * ASTB + aChunk;
        const uint32_t uAl = uAh + TILE_B;
        const uint32_t uBh = stg + 2*TILE_B + (wn + bRow) * ASTB + bChunk;

#pragma unroll
        for (int ks = 0; ks < 4; ks++) {
            const int kb = ks * 32;
            uint32_t aH[4][4], aL[4][4], bH[2][4];
#pragma unroll
            for (int mt = 0; mt < 4; mt++) {
                ldsm4(aH[mt], uAh + mt * (16*ASTB) + kb);
                if (J.npass == 2) ldsm4(aL[mt], uAl + mt * (16*ASTB) + kb);
            }
#pragma unroll
            for (int p = 0; p < 2; p++)
                ldsm4(bH[p], uBh + p * (16*ASTB) + kb);
#pragma unroll
            for (int mt = 0; mt < 4; mt++)
#pragma unroll
                for (int p = 0; p < 2; p++)
#pragma unroll
                    for (int hf = 0; hf < 2; hf++) {
                        int nt = p * 2 + hf;
                        uint32_t b0h = bH[p][2*hf], b1h = bH[p][2*hf+1];
                        mma_f16(acc[mt][nt], aH[mt], b0h, b1h);
                        if (J.npass == 2) mma_f16(acc[mt][nt], aL[mt], b0h, b1h);
                    }
        }
        __syncthreads();
    }

    const int ar = l >> 2;
#pragma unroll
    for (int mt = 0; mt < 4; mt++) {
        int gr0 = row0 + wm + mt * 16 + ar;
#pragma unroll
        for (int nt = 0; nt < 4; nt++) {
            int gc = col0 + wn + nt * 8 + (l & 3) * 2;
            float b0 = J.bias[gc], b1 = J.bias[gc + 1];
            float x0 = acc[mt][nt][0] + b0, y0 = acc[mt][nt][1] + b1;
            float x1 = acc[mt][nt][2] + b0, y1 = acc[mt][nt][3] + b1;
            size_t oA = (size_t)gr0 * DMODEL + gc;
            size_t oB = (size_t)(gr0 + 8) * DMODEL + gc;
            if (J.mode == 0) {
                *(float2*)(J.C + oA) = make_float2(x0, y0);
                *(float2*)(J.C + oB) = make_float2(x1, y1);
            } else if (J.mode == 2) {
                uint32_t h0, l0w, h1, l1w;
                split2h(x0, y0, h0, l0w);
                split2h(x1, y1, h1, l1w);
                ((uint32_t*)J.Ch)[oA >> 1] = h0;
                ((uint32_t*)J.Cl)[oA >> 1] = l0w;
                ((uint32_t*)J.Ch)[oB >> 1] = h1;
                ((uint32_t*)J.Cl)[oB >> 1] = l1w;
            } else {
                ((uint32_t*)J.Ch)[oA >> 1] = packh(x0, y0);
                ((uint32_t*)J.Ch)[oB >> 1] = packh(x1, y1);
            }
        }
    }
}

// ======================= fp16 HMMA flash attention =========================
// Q fp16 hi (registers), K fp16 hi, V fp16 hi natural layout (trans ldmatrix).
// QK 1-pass, PV 1-pass. Raw-score softmax (0.125 folded into exp via FMA),
// conditional output rescale. 2 CTAs/SM.
#define BQ  128
#define BKV 64
#define NKV (SEQ/BKV)          // 32
#define STB 144                // smem row stride bytes (72 halves)
#define QTILE_B (128*STB)      // 18432
#define KTILE_B (64*STB)       // 9216
#define STAGE_AB (2*KTILE_B)   // 18432 : Kh, Vh
#define ATTN_SMEM_B (QTILE_B + 2*STAGE_AB)   // 55296

__global__ __launch_bounds__(256, 2)
void attn_mma_kernel(const __half* __restrict__ Qh,
                     const __half* __restrict__ Kh,
                     const __half* __restrict__ Vh,
                     __half* __restrict__ Oh,
                     __half* __restrict__ Ol)
{
    extern __shared__ char smem[];
    const uint32_t sb = s2u(smem);
    const int t = threadIdx.x, w = t >> 5, l = t & 31;
    const int q0 = blockIdx.x * BQ;
    const int h  = blockIdx.y, b = blockIdx.z;
    const int r4 = l >> 2;

    // ---- prologue: Q hi into smem ----
    {
        const __half* QhG = Qh + ((size_t)(b*SEQ + q0)) * DMODEL + h*DHEAD;
#pragma unroll
        for (int i = 0; i < 4; i++) {
            int u = t + i * 256;               // 0..1023
            int row = u >> 3, ch = u & 7;
            uint32_t dst = sb + row * STB + ch * 16;
            cp16(dst, QhG + (size_t)row * DMODEL + ch * 8);
        }
    }
    auto load_kv = [&](int kvt, int st) {
        const uint32_t base = sb + QTILE_B + st * STAGE_AB;
        int kv0 = kvt * BKV;
        const __half* KhG = Kh + ((size_t)(b*SEQ + kv0)) * DMODEL + h*DHEAD;
        const __half* VhG = Vh + ((size_t)(b*SEQ + kv0)) * DMODEL + h*DHEAD;
#pragma unroll
        for (int i = 0; i < 4; i++) {
            int u = t + i * 256;               // 0..1023
            int tile = u >> 9, v = u & 511;
            int row = v >> 3, ch = v & 7;
            uint32_t dst = base + tile * KTILE_B + row * STB + ch * 16;
            const __half* src = (tile == 0 ? KhG : VhG) + (size_t)row * DMODEL + ch * 8;
            cp16(dst, src);
        }
        asm volatile("cp.async.commit_group;\n" ::: "memory");
    };
    load_kv(0, 0);
    asm volatile("cp.async.wait_group 0;\n" ::: "memory");
    __syncthreads();

    // ldmatrix lane geometry
    const int aRow   = (l & 7) + ((l >> 3) & 1) * 8;
    const int aChunk = (l >> 4) * 16;
    const int bRow   = (l & 7) + ((l >> 4) << 3);
    const int bChunk = ((l >> 3) & 1) * 16;

    // ---- Q fragments (held in registers for all kv tiles) ----
    uint32_t aH[4][4];
    {
        const uint32_t qoff = sb + (w * 16 + aRow) * STB + aChunk;
#pragma unroll
        for (int s = 0; s < 4; s++)
            ldsm4(aH[s], qoff + 32 * s);
    }

    float m0 = -1e30f, m1 = -1e30f, l0 = 0.f, l1 = 0.f;   // m in RAW units
    float oacc[8][4];
#pragma unroll
    for (int j = 0; j < 8; j++)
#pragma unroll
        for (int k = 0; k < 4; k++) oacc[j][k] = 0.f;

    for (int kvt = 0; kvt < NKV; kvt++) {
        if (kvt + 1 < NKV) {
            load_kv(kvt + 1, (kvt + 1) & 1);
            asm volatile("cp.async.wait_group 1;\n" ::: "memory");
        } else {
            asm volatile("cp.async.wait_group 0;\n" ::: "memory");
        }
        __syncthreads();

        const uint32_t stg = sb + QTILE_B + (kvt & 1) * STAGE_AB;
        const uint32_t uKh = stg + bRow * STB + bChunk;
        const uint32_t uVt = stg + KTILE_B + aRow * STB + aChunk;

        // ---- scores: S_raw = Qh*Kh (1-pass) ----
        float sc[8][4];
#pragma unroll
        for (int j = 0; j < 8; j++)
#pragma unroll
            for (int k = 0; k < 4; k++) sc[j][k] = 0.f;

#pragma unroll
        for (int jp = 0; jp < 4; jp++) {
#pragma unroll
            for (int s = 0; s < 4; s++) {
                uint32_t kh[4];
                ldsm4(kh, uKh + jp * 2304 + 32 * s);
                mma_f16(sc[2*jp],   aH[s], kh[0], kh[1]);
                mma_f16(sc[2*jp+1], aH[s], kh[2], kh[3]);
            }
        }

        // ---- online softmax on raw scores (scale folded into exp) ----
        float lm0 = -1e30f, lm1 = -1e30f;
#pragma unroll
        for (int j = 0; j < 8; j++) {
            lm0 = fmaxf(lm0, fmaxf(sc[j][0], sc[j][1]));
            lm1 = fmaxf(lm1, fmaxf(sc[j][2], sc[j][3]));
        }
        lm0 = fmaxf(lm0, __shfl_xor_sync(0xffffffffu, lm0, 1));
        lm0 = fmaxf(lm0, __shfl_xor_sync(0xffffffffu, lm0, 2));
        lm1 = fmaxf(lm1, __shfl_xor_sync(0xffffffffu, lm1, 1));
        lm1 = fmaxf(lm1, __shfl_xor_sync(0xffffffffu, lm1, 2));
        float mn0 = fmaxf(m0, lm0), mn1 = fmaxf(m1, lm1);

        float cf0 = 1.f, cf1 = 1.f;
        if (mn0 > m0 || mn1 > m1) {
            cf0 = __expf(0.125f * (m0 - mn0));
            cf1 = __expf(0.125f * (m1 - mn1));
#pragma unroll
            for (int j = 0; j < 8; j++) {
                oacc[j][0] *= cf0;  oacc[j][1] *= cf0;
                oacc[j][2] *= cf1;  oacc[j][3] *= cf1;
            }
            m0 = mn0;  m1 = mn1;
        }
        float h0 = -0.125f * mn0, h1 = -0.125f * mn1;
        float rs0 = 0.f, rs1 = 0.f;
#pragma unroll
        for (int j = 0; j < 8; j++) {
            float p0 = __expf(fmaf(sc[j][0], 0.125f, h0));
            float p1 = __expf(fmaf(sc[j][1], 0.125f, h0));
            float p2 = __expf(fmaf(sc[j][2], 0.125f, h1));
            float p3 = __expf(fmaf(sc[j][3], 0.125f, h1));
            sc[j][0] = p0; sc[j][1] = p1; sc[j][2] = p2; sc[j][3] = p3;
            rs0 += p0 + p1;  rs1 += p2 + p3;
        }
        rs0 += __shfl_xor_sync(0xffffffffu, rs0, 1);
        rs0 += __shfl_xor_sync(0xffffffffu, rs0, 2);
        rs1 += __shfl_xor_sync(0xffffffffu, rs1, 1);
        rs1 += __shfl_xor_sync(0xffffffffu, rs1, 2);
        l0 = l0 * cf0 + rs0;  l1 = l1 * cf1 + rs1;

        // ---- PV: ctx += P @ V (1-pass, V via trans ldmatrix), P fp16 ----
#pragma unroll
        for (int s = 0; s < 4; s++) {
            uint32_t pH[4];
            pH[0] = packh(sc[2*s][0],   sc[2*s][1]);
            pH[1] = packh(sc[2*s][2],   sc[2*s][3]);
            pH[2] = packh(sc[2*s+1][0], sc[2*s+1][1]);
            pH[3] = packh(sc[2*s+1][2], sc[2*s+1][3]);
#pragma unroll
            for (int jp = 0; jp < 4; jp++) {
                uint32_t vh[4];
                ldsm4t(vh, uVt + s * (16*STB) + jp * 32);
                mma_f16(oacc[2*jp],   pH, vh[0], vh[1]);
                mma_f16(oacc[2*jp+1], pH, vh[2], vh[3]);
            }
        }
        __syncthreads();
    }

    // ---- epilogue: divide by l, split to fp16 hi/lo, write [b,s,h*64+d] ----
    float inv0 = 1.0f / l0, inv1 = 1.0f / l1;
    const size_t rA = (size_t)(b*SEQ + q0 + w*16 + r4) * DMODEL + h*DHEAD + (l & 3) * 2;
    const size_t rB = rA + 8 * DMODEL;
#pragma unroll
    for (int j = 0; j < 8; j++) {
        uint32_t h0, l0w, h1, l1w;
        split2h(oacc[j][0] * inv0, oacc[j][1] * inv0, h0, l0w);
        split2h(oacc[j][2] * inv1, oacc[j][3] * inv1, h1, l1w);
        *(uint32_t*)(Oh + rA + j*8) = h0;
        *(uint32_t*)(Ol + rA + j*8) = l0w;
        *(uint32_t*)(Oh + rB + j*8) = h1;
        *(uint32_t*)(Ol + rB + j*8) = l1w;
    }
}

// =========================== launch ========================================
extern "C" void kernel_launch(void* const* d_in, const int* in_sizes, int n_in,
                              void* d_out, int out_size)
{
    (void)in_sizes; (void)n_in; (void)out_size;

    const float* qx = (const float*)d_in[0];
    const float* kx = (const float*)d_in[1];
    const float* vx = (const float*)d_in[2];
    const float* Wq = (const float*)d_in[3];
    const float* bq = (const float*)d_in[4];
    const float* Wk = (const float*)d_in[5];
    const float* bk = (const float*)d_in[6];
    const float* Wv = (const float*)d_in[7];
    const float* bv = (const float*)d_in[8];
    const float* Wo = (const float*)d_in[9];
    const float* bo = (const float*)d_in[10];
    float* out = (float*)d_out;

    __half *aqh, *aql, *akh, *avh;
    __half *wqh, *wkh, *wvh, *woh;
    __half *qh, *kh, *vh;
    cudaGetSymbolAddress((void**)&aqh, g_aqh);
    cudaGetSymbolAddress((void**)&aql, g_aql);
    cudaGetSymbolAddress((void**)&akh, g_akh);
    cudaGetSymbolAddress((void**)&avh, g_avh);
    cudaGetSymbolAddress((void**)&wqh, g_wqh);
    cudaGetSymbolAddress((void**)&wkh, g_wkh);
    cudaGetSymbolAddress((void**)&wvh, g_wvh);
    cudaGetSymbolAddress((void**)&woh, g_woh);
    cudaGetSymbolAddress((void**)&qh,  g_qh);
    cudaGetSymbolAddress((void**)&kh,  g_kh);
    cudaGetSymbolAddress((void**)&vh,  g_vh);

    cudaFuncSetAttribute(gemm_mma_kernel,
                         cudaFuncAttributeMaxDynamicSharedMemorySize, GEMM_SMEM);
    cudaFuncSetAttribute(attn_mma_kernel,
                         cudaFuncAttributeMaxDynamicSharedMemorySize, ATTN_SMEM_B);

    const int n4 = MROWS * DMODEL / 4;

    // fused conversions: activations (3) + all four weights (1 launch)
    split3_kernel<<<dim3(n4/256, 3), 256>>>(qx, kx, vx,
                                            aqh, aql, akh, avh, n4);
    wtsplit4_kernel<<<dim3(32, 32, 4), 256>>>(Wq, Wk, Wv, Wo,
                                              wqh, wkh, wvh, woh);

    // fused QKV projections (Q 2-pass input -> fp16 hi; K,V 1-pass -> fp16 hi)
    GemmJob jq = {aqh, aql, wqh, bq, nullptr, qh, nullptr, 3, 2};
    GemmJob jk = {akh, nullptr, wkh, bk, nullptr, kh, nullptr, 3, 1};
    GemmJob jv = {avh, nullptr, wvh, bv, nullptr, vh, nullptr, 3, 1};
    gemm_mma_kernel<<<dim3(8, 32, 3), 256, GEMM_SMEM>>>(jq, jk, jv);

    // attention -> ctx fp16 hi/lo straight into final-GEMM input buffers
    attn_mma_kernel<<<dim3(SEQ/BQ, NH, BATCH), 256, ATTN_SMEM_B>>>(
        qh, kh, vh, aqh, aql);

    // output projection (2-pass, fp32 out)
    GemmJob jo = {aqh, aql, woh, bo, out, nullptr, nullptr, 0, 2};
    gemm_mma_kernel<<<dim3(8, 32, 1), 256, GEMM_SMEM>>>(jo, jo, jo);
}